// round 14
// baseline (speedup 1.0000x reference)
#include <cuda_runtime.h>
#include <cuda_bf16.h>
#include <math.h>
#include <stdint.h>

#define QLEN   1024
#define DMODEL 1024
#define DFF    4096
#define ROWS   4096
#define D3     3072

typedef __nv_bfloat16 bf16;

__device__ float g_tmp[(size_t)ROWS * DMODEL];
__device__ float g_out1[(size_t)ROWS * DMODEL];

__device__ bf16 g_wh[(size_t)ROWS * DMODEL],   g_wl[(size_t)ROWS * DMODEL];
__device__ bf16 g_rh[(size_t)QLEN * DMODEL],   g_rl[(size_t)QLEN * DMODEL];
__device__ bf16 g_qwh[(size_t)D3 * DMODEL],    g_qwl[(size_t)D3 * DMODEL];
__device__ bf16 g_rwh[(size_t)DMODEL * DMODEL],g_rwl[(size_t)DMODEL * DMODEL];
__device__ bf16 g_owh[(size_t)DMODEL * DMODEL],g_owl[(size_t)DMODEL * DMODEL];
__device__ bf16 g_f1h[(size_t)DFF * DMODEL],   g_f1l[(size_t)DFF * DMODEL];
__device__ bf16 g_f2h[(size_t)DMODEL * DFF],   g_f2l[(size_t)DMODEL * DFF];
__device__ bf16 g_hh[(size_t)ROWS * D3],       g_hl[(size_t)ROWS * D3];
__device__ bf16 g_rkh[(size_t)QLEN * DMODEL],  g_rkl[(size_t)QLEN * DMODEL];
__device__ bf16 g_avh[(size_t)ROWS * DMODEL],  g_avl[(size_t)ROWS * DMODEL];
__device__ bf16 g_o1h[(size_t)ROWS * DMODEL],  g_o1l[(size_t)ROWS * DMODEL];
__device__ bf16 g_ff1h[(size_t)ROWS * DFF],    g_ff1l[(size_t)ROWS * DFF];

__device__ __forceinline__ uint32_t cvta_smem(const void* p) {
    uint32_t a;
    asm("{ .reg .u64 t; cvta.to.shared.u64 t, %1; cvt.u32.u64 %0, t; }"
        : "=r"(a) : "l"(p));
    return a;
}
#define SWZ(o)   ((o) ^ (((o) >> 3) & 0x70))   // 128B rows (flash)
#define SWZ64(o) ((o) ^ (((o) >> 3) & 0x30))   // 64B rows (dense KC=32)

__device__ __forceinline__ void cp16(uint32_t dst, const void* src) {
    asm volatile("cp.async.cg.shared.global [%0], [%1], 16;" :: "r"(dst), "l"(src));
}
__device__ __forceinline__ void cp16z(uint32_t dst, const void* src, uint32_t sz) {
    asm volatile("cp.async.cg.shared.global [%0], [%1], 16, %2;"
                 :: "r"(dst), "l"(src), "r"(sz));
}
__device__ __forceinline__ void cp_commit() {
    asm volatile("cp.async.commit_group;" ::: "memory");
}
template <int N> __device__ __forceinline__ void cp_wait() {
    asm volatile("cp.async.wait_group %0;" :: "n"(N) : "memory");
}
__device__ __forceinline__ void bar_pair(int id) {
    asm volatile("bar.sync %0, 64;" :: "r"(id) : "memory");
}
__device__ __forceinline__ void ldsm_x4(uint32_t& r0, uint32_t& r1,
                                        uint32_t& r2, uint32_t& r3, uint32_t a) {
    asm volatile("ldmatrix.sync.aligned.m8n8.x4.shared.b16 {%0,%1,%2,%3}, [%4];"
                 : "=r"(r0), "=r"(r1), "=r"(r2), "=r"(r3) : "r"(a));
}
__device__ __forceinline__ void ldsm_x2(uint32_t& r0, uint32_t& r1, uint32_t a) {
    asm volatile("ldmatrix.sync.aligned.m8n8.x2.shared.b16 {%0,%1}, [%2];"
                 : "=r"(r0), "=r"(r1) : "r"(a));
}
__device__ __forceinline__ void ldsm_x2t(uint32_t& r0, uint32_t& r1, uint32_t a) {
    asm volatile("ldmatrix.sync.aligned.m8n8.x2.trans.shared.b16 {%0,%1}, [%2];"
                 : "=r"(r0), "=r"(r1) : "r"(a));
}
__device__ __forceinline__ void mma_bf16(float* c, uint32_t a0, uint32_t a1,
                                         uint32_t a2, uint32_t a3,
                                         uint32_t b0, uint32_t b1) {
    asm volatile(
        "mma.sync.aligned.m16n8k16.row.col.f32.bf16.bf16.f32 "
        "{%0,%1,%2,%3}, {%4,%5,%6,%7}, {%8,%9}, {%0,%1,%2,%3};"
        : "+f"(c[0]), "+f"(c[1]), "+f"(c[2]), "+f"(c[3])
        : "r"(a0), "r"(a1), "r"(a2), "r"(a3), "r"(b0), "r"(b1));
}
__device__ __forceinline__ void split2(float x, float y, uint32_t& h, uint32_t& l) {
    bf16 hx = __float2bfloat16_rn(x), hy = __float2bfloat16_rn(y);
    bf16 lx = __float2bfloat16_rn(x - __bfloat162float(hx));
    bf16 ly = __float2bfloat16_rn(y - __bfloat162float(hy));
    __nv_bfloat162 hp; hp.x = hx; hp.y = hy;
    __nv_bfloat162 lp; lp.x = lx; lp.y = ly;
    h = *(uint32_t*)&hp; l = *(uint32_t*)&lp;
}

// -------- dense GEMM v4: KC=32, SW64, 3 stages, 2 CTAs/SM ------------------
#define TM 128
#define TN 128
#define KC 32
#define STAGES 3
#define GT 256
#define ARRB    8192                         // 128 rows x 64B (KC=32 bf16)
#define STGSZ   (4 * ARRB)                   // 32768 per stage
#define SM_S    1024
#define GEMM_SMEM (SM_S + STAGES * STGSZ)    // 99328 -> 2 CTAs/SM

template <bool BIAS, bool RELU, bool OUTF, bool OUTS>
__global__ __launch_bounds__(GT, 2) void gemm_tc(
    const bf16* __restrict__ Ah, const bf16* __restrict__ Al,
    const bf16* __restrict__ Bh, const bf16* __restrict__ Bl,
    const float* __restrict__ bias, float* __restrict__ C,
    bf16* __restrict__ Ch, bf16* __restrict__ Cl, int N, int K)
{
    extern __shared__ char smem[];
    const uint32_t sbase = cvta_smem(smem);
    const int tid  = threadIdx.x;
    const int lane = tid & 31;
    const int warp = tid >> 5;
    const int wm   = warp >> 2, wn = warp & 3;
    const int i0   = blockIdx.y * TM, j0 = blockIdx.x * TN;

    if (BIAS) { if (tid < TN) ((float*)smem)[tid] = bias[j0 + tid]; }

    const int NC = K / KC;
    const bf16* srcs[4] = { Ah + (size_t)i0 * K, Al + (size_t)i0 * K,
                            Bh + (size_t)j0 * K, Bl + (size_t)j0 * K };

    auto load_chunk = [&](int c) {
        const uint32_t stb = sbase + SM_S + (c % STAGES) * STGSZ;
        const int kc = c * KC;
#pragma unroll
        for (int it = 0; it < 8; it++) {
            int s = tid + it * GT;                  // 0..2047
            int arr = s >> 9, sect = s & 511;
            int row = sect >> 2, sc = sect & 3;     // 128 rows x 4 x 16B
            cp16(stb + arr * ARRB + SWZ64(row * 64 + sc * 16),
                 (const char*)(srcs[arr] + (size_t)row * K + kc) + sc * 16);
        }
    };

    float acc[4][4][4];
#pragma unroll
    for (int mt = 0; mt < 4; mt++)
#pragma unroll
        for (int nt = 0; nt < 4; nt++)
#pragma unroll
            for (int e = 0; e < 4; e++) acc[mt][nt][e] = 0.0f;

#pragma unroll
    for (int c = 0; c < STAGES - 1; c++) { load_chunk(c); cp_commit(); }

    const int a_row = wm * 64 + (lane & 15);
    const int a_ko  = (lane >> 4) * 16;
    const int b_row = wn * 32 + (lane & 7);
    const int b_ko  = ((lane >> 3) & 1) * 16;

    for (int c = 0; c < NC; c++) {
        const int cl = c + STAGES - 1;
        if (cl < NC) load_chunk(cl);
        cp_commit();
        cp_wait<STAGES - 1>();
        __syncthreads();
        const uint32_t stb = sbase + SM_S + (c % STAGES) * STGSZ;
#pragma unroll
        for (int ks = 0; ks < 2; ks++) {
            uint32_t bh[4][2], bl[4][2];
#pragma unroll
            for (int nt = 0; nt < 4; nt++) {
                uint32_t off = SWZ64((b_row + nt * 8) * 64 + ks * 32 + b_ko);
                ldsm_x2(bh[nt][0], bh[nt][1], stb + 2 * ARRB + off);
                ldsm_x2(bl[nt][0], bl[nt][1], stb + 3 * ARRB + off);
            }
#pragma unroll
            for (int mt = 0; mt < 4; mt++) {
                uint32_t off = SWZ64((a_row + mt * 16) * 64 + ks * 32 + a_ko);
                uint32_t ah0, ah1, ah2, ah3, al0, al1, al2, al3;
                ldsm_x4(ah0, ah1, ah2, ah3, stb + off);
                ldsm_x4(al0, al1, al2, al3, stb + ARRB + off);
#pragma unroll
                for (int nt = 0; nt < 4; nt++) {
                    mma_bf16(acc[mt][nt], ah0, ah1, ah2, ah3, bh[nt][0], bh[nt][1]);
                    mma_bf16(acc[mt][nt], ah0, ah1, ah2, ah3, bl[nt][0], bl[nt][1]);
                    mma_bf16(acc[mt][nt], al0, al1, al2, al3, bh[nt][0], bh[nt][1]);
                }
            }
        }
        __syncthreads();
    }

    const int er = lane >> 2, ec = (lane & 3) * 2;
#pragma unroll
    for (int mt = 0; mt < 4; mt++) {
#pragma unroll
        for (int nt = 0; nt < 4; nt++) {
            const int col = wn * 32 + nt * 8 + ec;
            float b0 = 0.0f, b1 = 0.0f;
            if (BIAS) { b0 = ((float*)smem)[col]; b1 = ((float*)smem)[col + 1]; }
#pragma unroll
            for (int h = 0; h < 2; h++) {
                const int row = i0 + wm * 64 + mt * 16 + er + h * 8;
                float v0 = acc[mt][nt][2 * h] + b0;
                float v1 = acc[mt][nt][2 * h + 1] + b1;
                if (RELU) { v0 = fmaxf(v0, 0.0f); v1 = fmaxf(v1, 0.0f); }
                if (OUTF)
                    *(float2*)(C + (size_t)row * N + j0 + col) = make_float2(v0, v1);
                if (OUTS) {
                    uint32_t hh, ll;
                    split2(v0, v1, hh, ll);
                    *(uint32_t*)(Ch + (size_t)row * N + j0 + col) = hh;
                    *(uint32_t*)(Cl + (size_t)row * N + j0 + col) = ll;
                }
            }
        }
    }
}

// -------- batched split: all 7 tensors, descriptors passed BY VALUE --------
struct SplitDesc { const float4* x; uint2* h; uint2* l; int base; int pad; };
struct SplitArgs { SplitDesc d[7]; };

__global__ __launch_bounds__(256) void split_all(SplitArgs args, int total4)
{
    int i = blockIdx.x * 256 + threadIdx.x;
    if (i >= total4) return;
    int seg = 0;
#pragma unroll
    for (int s = 1; s < 7; s++) if (i >= args.d[s].base) seg = s;
    int k = i - args.d[seg].base;
    float4 v = args.d[seg].x[k];
    uint32_t h01, l01, h23, l23;
    split2(v.x, v.y, h01, l01);
    split2(v.z, v.w, h23, l23);
    args.d[seg].h[k] = make_uint2(h01, h23);
    args.d[seg].l[k] = make_uint2(l01, l23);
}

// ------------------------- fused flash attention (R8) ----------------------
#define FQWH 0
#define FQWL 8192
#define FQRH 16384
#define FQRL 24576
#define FKV  32768
#define FRK  98304
#define FDT  163840
#define FSTM 197632
#define FSTS 198144
#define FLASH_SMEM 198656

__global__ __launch_bounds__(256) void flash_attn(
    const bf16* __restrict__ hh, const bf16* __restrict__ hl,
    const bf16* __restrict__ rkh, const bf16* __restrict__ rkl,
    const float* __restrict__ rwb, const float* __restrict__ rrb,
    bf16* __restrict__ avh, bf16* __restrict__ avl)
{
    extern __shared__ char sm[];
    const uint32_t sb = cvta_smem(sm);
    const int tid = threadIdx.x, lane = tid & 31, w = tid >> 5;
    const int wr = w >> 1, wc = w & 1;
    const int ib = 15 - (int)blockIdx.x;
    const int bn = blockIdx.y, b = bn >> 4, n = bn & 15;
    const int i0 = ib * 64;
    const int tw0 = QLEN - 64 - i0;
    const int ntiles = ib + 1;
    const size_t bq = (size_t)b * QLEN;
    const int barid = wr + 1;

    auto load_kv = [&](int jt) {
        const uint32_t dstb = sb + FKV + (jt & 1) * 32768;
#pragma unroll
        for (int it = 0; it < 8; it++) {
            int s = tid + it * 256;
            int arr = s >> 9, sect = s & 511;
            int row = sect >> 3, sc = sect & 7;
            const bf16* src = ((arr & 1) ? hl : hh) +
                (bq + jt * 64 + row) * D3 + ((arr >> 1) + 1) * DMODEL + n * 64;
            cp16(dstb + arr * 8192 + SWZ(row * 128 + sc * 16),
                 (const char*)src + sc * 16);
        }
    };
    auto load_rk = [&](int tile) {
        const uint32_t dstb = sb + FRK + (tile & 3) * 16384;
#pragma unroll
        for (int it = 0; it < 4; it++) {
            int s = tid + it * 256;
            int arr = s >> 9, sect = s & 511;
            int row = sect >> 3, sc = sect & 7;
            int t = tw0 + tile * 64 + row;
            int tc = (t < QLEN) ? t : 0;
            const bf16* src = (arr ? rkl : rkh) + (size_t)tc * DMODEL + n * 64;
            cp16z(dstb + arr * 8192 + SWZ(row * 128 + sc * 16),
                  (const char*)src + sc * 16, (t < QLEN) ? 16u : 0u);
        }
    };

    load_kv(0); load_rk(0); load_rk(1); cp_commit();

#pragma unroll
    for (int it = 0; it < 4; it++) {
        int s = tid + it * 256;
        int row = s >> 4, c4 = (s & 15) << 2;
        const size_t qoff = (bq + i0 + row) * D3 + n * 64 + c4;
        uint2 qh = *(const uint2*)(hh + qoff);
        uint2 ql = *(const uint2*)(hl + qoff);
        __nv_bfloat162 h01 = *(__nv_bfloat162*)&qh.x, h23 = *(__nv_bfloat162*)&qh.y;
        __nv_bfloat162 l01 = *(__nv_bfloat162*)&ql.x, l23 = *(__nv_bfloat162*)&ql.y;
        float q0 = __bfloat162float(h01.x) + __bfloat162float(l01.x);
        float q1 = __bfloat162float(h01.y) + __bfloat162float(l01.y);
        float q2 = __bfloat162float(h23.x) + __bfloat162float(l23.x);
        float q3 = __bfloat162float(h23.y) + __bfloat162float(l23.y);
        float4 bw = *(const float4*)(rwb + n * 64 + c4);
        float4 br = *(const float4*)(rrb + n * 64 + c4);
        uint32_t a01, b01, a23, b23;
        uint32_t off = SWZ(row * 128 + c4 * 2);
        split2((q0 + bw.x) * 0.125f, (q1 + bw.y) * 0.125f, a01, b01);
        split2((q2 + bw.z) * 0.125f, (q3 + bw.w) * 0.125f, a23, b23);
        *(uint2*)(sm + FQWH + off) = make_uint2(a01, a23);
        *(uint2*)(sm + FQWL + off) = make_uint2(b01, b23);
        split2((q0 + br.x) * 0.125f, (q1 + br.y) * 0.125f, a01, b01);
        split2((q2 + br.z) * 0.125f, (q3 + br.w) * 0.125f, a23, b23);
        *(uint2*)(sm + FQRH + off) = make_uint2(a01, a23);
        *(uint2*)(sm + FQRL + off) = make_uint2(b01, b23);
    }

    float m0 = -INFINITY, m1 = -INFINITY, l0 = 0.0f, l1 = 0.0f;
    float accO[8][4];
#pragma unroll
    for (int nt = 0; nt < 8; nt++)
#pragma unroll
        for (int e = 0; e < 4; e++) accO[nt][e] = 0.0f;

    const int r0 = lane >> 2, c00 = (lane & 3) * 2;
    const uint32_t aoff = (wr * 16 + (lane & 15)) * 128 + ((lane >> 4) << 4);
    const uint32_t bko  = ((lane >> 3) & 1) << 4;
    const int u0 = 6 - 2 * wr;
    float* dwp = (float*)(sm + FDT + wr * 8448);
    float* stM = (float*)(sm + FSTM);
    float* stS = (float*)(sm + FSTS);

    for (int jt = 0; jt < ntiles; jt++) {
        cp_wait<0>();
        __syncthreads();
        if (jt + 1 < ntiles) { load_kv(jt + 1); load_rk(jt + 2); }
        cp_commit();

        const uint32_t kvb = sb + FKV + (jt & 1) * 32768;
        float aS[4][4];
#pragma unroll
        for (int nt = 0; nt < 4; nt++)
#pragma unroll
            for (int e = 0; e < 4; e++) aS[nt][e] = 0.0f;
#pragma unroll
        for (int kc = 0; kc < 4; kc++) {
            uint32_t ah0, ah1, ah2, ah3, al0, al1, al2, al3;
            ldsm_x4(ah0, ah1, ah2, ah3, sb + FQWH + SWZ(aoff + kc * 32));
            ldsm_x4(al0, al1, al2, al3, sb + FQWL + SWZ(aoff + kc * 32));
#pragma unroll
            for (int nt = 0; nt < 4; nt++) {
                uint32_t boff = (wc * 32 + nt * 8 + (lane & 7)) * 128 + kc * 32 + bko;
                uint32_t b0, b1;
                ldsm_x2(b0, b1, kvb + SWZ(boff));
                mma_bf16(aS[nt], ah0, ah1, ah2, ah3, b0, b1);
                mma_bf16(aS[nt], al0, al1, al2, al3, b0, b1);
                ldsm_x2(b0, b1, kvb + 8192 + SWZ(boff));
                mma_bf16(aS[nt], ah0, ah1, ah2, ah3, b0, b1);
            }
        }

        float aB[5][4];
#pragma unroll
        for (int v = 0; v < 5; v++)
#pragma unroll
            for (int e = 0; e < 4; e++) aB[v][e] = 0.0f;
#pragma unroll
        for (int kc = 0; kc < 4; kc++) {
            uint32_t ah0, ah1, ah2, ah3, al0, al1, al2, al3;
            ldsm_x4(ah0, ah1, ah2, ah3, sb + FQRH + SWZ(aoff + kc * 32));
            ldsm_x4(al0, al1, al2, al3, sb + FQRL + SWZ(aoff + kc * 32));
#pragma unroll
            for (int v = 0; v < 5; v++) {
                int cu = u0 + wc * 5 + v;
                uint32_t rbase = sb + FRK + ((jt + (cu >> 3)) & 3) * 16384;
                uint32_t boff = ((cu & 7) * 8 + (lane & 7)) * 128 + kc * 32 + bko;
                uint32_t b0, b1;
                ldsm_x2(b0, b1, rbase + SWZ(boff));
                mma_bf16(aB[v], ah0, ah1, ah2, ah3, b0, b1);
                mma_bf16(aB[v], al0, al1, al2, al3, b0, b1);
                ldsm_x2(b0, b1, rbase + 8192 + SWZ(boff));
                mma_bf16(aB[v], ah0, ah1, ah2, ah3, b0, b1);
            }
        }
#pragma unroll
        for (int v = 0; v < 5; v++) {
            int col = (u0 + wc * 5 + v) * 8 + c00;
            dwp[r0 * 132 + col]           = aB[v][0];
            dwp[r0 * 132 + col + 1]       = aB[v][1];
            dwp[(r0 + 8) * 132 + col]     = aB[v][2];
            dwp[(r0 + 8) * 132 + col + 1] = aB[v][3];
        }
        bar_pair(barid);

        const int s0 = 63 - wr * 16 - r0, s1 = s0 - 8;
        const int gi0 = i0 + wr * 16 + r0, gi1 = gi0 + 8;
        const int j0 = jt * 64;
        float tm0 = -INFINITY, tm1 = -INFINITY;
#pragma unroll
        for (int nt = 0; nt < 4; nt++) {
            int cb = wc * 32 + nt * 8 + c00;
            float v0 = aS[nt][0] + dwp[r0 * 132 + cb + s0];
            float v1 = aS[nt][1] + dwp[r0 * 132 + cb + 1 + s0];
            float v2 = aS[nt][2] + dwp[(r0 + 8) * 132 + cb + s1];
            float v3 = aS[nt][3] + dwp[(r0 + 8) * 132 + cb + 1 + s1];
            if (j0 + cb     > gi0) v0 = -INFINITY;
            if (j0 + cb + 1 > gi0) v1 = -INFINITY;
            if (j0 + cb     > gi1) v2 = -INFINITY;
            if (j0 + cb + 1 > gi1) v3 = -INFINITY;
            aS[nt][0] = v0; aS[nt][1] = v1; aS[nt][2] = v2; aS[nt][3] = v3;
            tm0 = fmaxf(tm0, fmaxf(v0, v1));
            tm1 = fmaxf(tm1, fmaxf(v2, v3));
        }
        tm0 = fmaxf(tm0, __shfl_xor_sync(0xffffffffu, tm0, 1));
        tm0 = fmaxf(tm0, __shfl_xor_sync(0xffffffffu, tm0, 2));
        tm1 = fmaxf(tm1, __shfl_xor_sync(0xffffffffu, tm1, 1));
        tm1 = fmaxf(tm1, __shfl_xor_sync(0xffffffffu, tm1, 2));
        if ((lane & 3) == 0) {
            stM[(wr * 16 + r0) * 2 + wc]     = tm0;
            stM[(wr * 16 + r0 + 8) * 2 + wc] = tm1;
        }
        bar_pair(barid);
        float cm0 = fmaxf(stM[(wr * 16 + r0) * 2],     stM[(wr * 16 + r0) * 2 + 1]);
        float cm1 = fmaxf(stM[(wr * 16 + r0 + 8) * 2], stM[(wr * 16 + r0 + 8) * 2 + 1]);
        float mn0 = fmaxf(m0, cm0), mn1 = fmaxf(m1, cm1);
        float sc0 = __expf(m0 - mn0), sc1 = __expf(m1 - mn1);
        m0 = mn0; m1 = mn1;
        float ts0 = 0.0f, ts1 = 0.0f;
#pragma unroll
        for (int nt = 0; nt < 4; nt++) {
            float p0 = __expf(aS[nt][0] - m0);
            float p1 = __expf(aS[nt][1] - m0);
            float p2 = __expf(aS[nt][2] - m1);
            float p3 = __expf(aS[nt][3] - m1);
            aS[nt][0] = p0; aS[nt][1] = p1; aS[nt][2] = p2; aS[nt][3] = p3;
            ts0 += p0 + p1; ts1 += p2 + p3;
        }
        ts0 += __shfl_xor_sync(0xffffffffu, ts0, 1);
        ts0 += __shfl_xor_sync(0xffffffffu, ts0, 2);
        ts1 += __shfl_xor_sync(0xffffffffu, ts1, 1);
        ts1 += __shfl_xor_sync(0xffffffffu, ts1, 2);
        if ((lane & 3) == 0) {
            stS[(wr * 16 + r0) * 2 + wc]     = ts0;
            stS[(wr * 16 + r0 + 8) * 2 + wc] = ts1;
        }
        bar_pair(barid);
        float cs0 = stS[(wr * 16 + r0) * 2]     + stS[(wr * 16 + r0) * 2 + 1];
        float cs1 = stS[(wr * 16 + r0 + 8) * 2] + stS[(wr * 16 + r0 + 8) * 2 + 1];
        l0 = l0 * sc0 + cs0;
        l1 = l1 * sc1 + cs1;
#pragma unroll
        for (int nt = 0; nt < 8; nt++) {
            accO[nt][0] *= sc0; accO[nt][1] *= sc0;
            accO[nt][2] *= sc1; accO[nt][3] *= sc1;
        }

        uint32_t ph[2][4], pl[2][4];
#pragma unroll
        for (int kcl = 0; kcl < 2; kcl++) {
            split2(aS[2*kcl][0],   aS[2*kcl][1],   ph[kcl][0], pl[kcl][0]);
            split2(aS[2*kcl][2],   aS[2*kcl][3],   ph[kcl][1], pl[kcl][1]);
            split2(aS[2*kcl+1][0], aS[2*kcl+1][1], ph[kcl][2], pl[kcl][2]);
            split2(aS[2*kcl+1][2], aS[2*kcl+1][3], ph[kcl][3], pl[kcl][3]);
        }
#pragma unroll
        for (int kcl = 0; kcl < 2; kcl++) {
            uint32_t voff = (wc * 32 + kcl * 16 + (lane & 15)) * 128;
#pragma unroll
            for (int vnt = 0; vnt < 8; vnt++) {
                uint32_t b0, b1;
                ldsm_x2t(b0, b1, kvb + 16384 + SWZ(voff + vnt * 16));
                mma_bf16(accO[vnt], ph[kcl][0], ph[kcl][1], ph[kcl][2], ph[kcl][3], b0, b1);
                mma_bf16(accO[vnt], pl[kcl][0], pl[kcl][1], pl[kcl][2], pl[kcl][3], b0, b1);
                ldsm_x2t(b0, b1, kvb + 24576 + SWZ(voff + vnt * 16));
                mma_bf16(accO[vnt], ph[kcl][0], ph[kcl][1], ph[kcl][2], ph[kcl][3], b0, b1);
            }
        }
    }

    float* red = (float*)(sm + FDT + wr * 4096);
    if (wc == 1) {
#pragma unroll
        for (int nt = 0; nt < 8; nt++)
#pragma unroll
            for (int e = 0; e < 4; e++)
                red[(nt * 4 + e) * 32 + lane] = accO[nt][e];
    }
    __syncthreads();
    if (wc == 0) {
#pragma unroll
        for (int nt = 0; nt < 8; nt++)
#pragma unroll
            for (int e = 0; e < 4; e++)
                accO[nt][e] += red[(nt * 4 + e) * 32 + lane];
        const float inv0 = 1.0f / l0, inv1 = 1.0f / l1;
        const size_t row0 = (bq + i0 + wr * 16 + r0) * DMODEL + n * 64;
        const size_t row1 = row0 + 8 * DMODEL;
#pragma unroll
        for (int nt = 0; nt < 8; nt++) {
            int col = nt * 8 + c00;
            uint32_t hh2, ll2;
            split2(accO[nt][0] * inv0, accO[nt][1] * inv0, hh2, ll2);
            *(uint32_t*)(avh + row0 + col) = hh2;
            *(uint32_t*)(avl + row0 + col) = ll2;
            split2(accO[nt][2] * inv1, accO[nt][3] * inv1, hh2, ll2);
            *(uint32_t*)(avh + row1 + col) = hh2;
            *(uint32_t*)(avl + row1 + col) = ll2;
        }
    }
}

// ------------------------- residual + LayerNorm (2 rows/CTA) ---------------
template <bool SPLIT>
__global__ __launch_bounds__(512) void add_ln(
    const float* __restrict__ a, const float* __restrict__ bb,
    const float* __restrict__ gamma, const float* __restrict__ beta,
    float* __restrict__ out, bf16* __restrict__ oh, bf16* __restrict__ ol)
{
    const int row = blockIdx.x * 2 + (threadIdx.x >> 8);
    const size_t base = (size_t)row * DMODEL;
    const int tid = threadIdx.x & 255;
    const int half = threadIdx.x >> 8;
    __shared__ float red[2][8];

    float x[4];
    float sum = 0.0f;
#pragma unroll
    for (int c = 0; c < 4; c++) {
        int j = tid + (c << 8);
        x[c] = a[base + j] + bb[base + j];
        sum += x[c];
    }
#pragma unroll
    for (int o = 16; o; o >>= 1) sum += __shfl_xor_sync(0xffffffffu, sum, o);
    if ((tid & 31) == 0) red[half][tid >> 5] = sum;
    __syncthreads();
    float tot = red[half][0];
#pragma unroll
    for (int w = 1; w < 8; w++) tot += red[half][w];
    __syncthreads();
    const float mean = tot * (1.0f / DMODEL);

    float vs = 0.0f;
#pragma unroll
    for (int c = 0; c < 4; c++) { float d = x[c] - mean; vs += d * d; }
#pragma unroll
    for (int o = 16; o; o >>= 1) vs += __shfl_xor_sync(0xffffffffu, vs, o);
    if ((tid & 31) == 0) red[half][tid >> 5] = vs;
    __syncthreads();
    float vtot = red[half][0];
#pragma unroll
    for (int w = 1; w < 8; w++) vtot += red[half][w];
    const float rstd = rsqrtf(vtot * (1.0f / DMODEL) + 1e-5f);

#pragma unroll
    for (int c = 0; c < 4; c++) {
        int j = tid + (c << 8);
        float y = (x[c] - mean) * rstd * gamma[j] + beta[j];
        out[base + j] = y;
        if (SPLIT) {
            bf16 h = __float2bfloat16_rn(y);
            bf16 l = __float2bfloat16_rn(y - __bfloat162float(h));
            oh[base + j] = h; ol[base + j] = l;
        }
    }
}

// ------------------------------- launcher ----------------------------------
extern "C" void kernel_launch(void* const* d_in, const int* in_sizes, int n_in,
                              void* d_out, int out_size)
{
    (void)in_sizes; (void)n_in; (void)out_size;

    const float* w        = (const float*)d_in[0];
    const float* r        = (const float*)d_in[1];
    const float* qkv_w    = (const float*)d_in[3];
    const float* r_w      = (const float*)d_in[4];
    const float* o_w      = (const float*)d_in[5];
    const float* r_w_bias = (const float*)d_in[6];
    const float* r_r_bias = (const float*)d_in[7];
    const float* ln1_g    = (const float*)d_in[8];
    const float* ln1_b    = (const float*)d_in[9];
    const float* ff_w1    = (const float*)d_in[10];
    const float* ff_b1    = (const float*)d_in[11];
    const float* ff_w2    = (const float*)d_in[12];
    const float* ff_b2    = (const float*)d_in[13];
    const float* ln2_g    = (const float*)d_in[14];
    const float* ln2_b    = (const float*)d_in[15];
    float* out = (float*)d_out;

    float *tmp, *out1;
    cudaGetSymbolAddress((void**)&tmp,  g_tmp);
    cudaGetSymbolAddress((void**)&out1, g_out1);

    bf16 *wh, *wl, *rh, *rl, *qwh, *qwl, *rwh, *rwl, *owh, *owl;
    bf16 *f1h, *f1l, *f2h, *f2l, *avh, *avl, *o1h, *o1l, *ff1h, *ff1l;
    bf16 *hh, *hl, *rkh, *rkl;
    cudaGetSymbolAddress((void**)&wh,  g_wh);  cudaGetSymbolAddress((void**)&wl,  g_wl);
    cudaGetSymbolAddress((void**)&rh,  g_rh);  cudaGetSymbolAddress((void**)&rl,  g_rl);
    cudaGetSymbolAddress((void**)&qwh, g_qwh); cudaGetSymbolAddress((void**)&qwl, g_qwl);
    cudaGetSymbolAddress((void**)&rwh, g_rwh); cudaGetSymbolAddress((void**)&rwl, g_rwl);
    cudaGetSymbolAddress((void**)&owh, g_owh); cudaGetSymbolAddress((void**)&owl, g_owl);
    cudaGetSymbolAddress((void**)&f1h, g_f1h); cudaGetSymbolAddress((void**)&f1l, g_f1l);
    cudaGetSymbolAddress((void**)&f2h, g_f2h); cudaGetSymbolAddress((void**)&f2l, g_f2l);
    cudaGetSymbolAddress((void**)&avh, g_avh); cudaGetSymbolAddress((void**)&avl, g_avl);
    cudaGetSymbolAddress((void**)&o1h, g_o1h); cudaGetSymbolAddress((void**)&o1l, g_o1l);
    cudaGetSymbolAddress((void**)&ff1h, g_ff1h); cudaGetSymbolAddress((void**)&ff1l, g_ff1l);
    cudaGetSymbolAddress((void**)&hh,  g_hh);  cudaGetSymbolAddress((void**)&hl,  g_hl);
    cudaGetSymbolAddress((void**)&rkh, g_rkh); cudaGetSymbolAddress((void**)&rkl, g_rkl);

    cudaFuncSetAttribute(gemm_tc<false, false, false, true>,
                         cudaFuncAttributeMaxDynamicSharedMemorySize, GEMM_SMEM);
    cudaFuncSetAttribute(gemm_tc<false, false, true, false>,
                         cudaFuncAttributeMaxDynamicSharedMemorySize, GEMM_SMEM);
    cudaFuncSetAttribute(gemm_tc<true, true, false, true>,
                         cudaFuncAttributeMaxDynamicSharedMemorySize, GEMM_SMEM);
    cudaFuncSetAttribute(gemm_tc<true, false, true, false>,
                         cudaFuncAttributeMaxDynamicSharedMemorySize, GEMM_SMEM);
    cudaFuncSetAttribute(flash_attn,
                         cudaFuncAttributeMaxDynamicSharedMemorySize, FLASH_SMEM);

    // one batched split launch; descriptors passed by value (graph-safe)
    {
        SplitArgs sa;
        const float* xs[7] = { w, r, qkv_w, r_w, o_w, ff_w1, ff_w2 };
        bf16* hs[7] = { wh, rh, qwh, rwh, owh, f1h, f2h };
        bf16* ls[7] = { wl, rl, qwl, rwl, owl, f1l, f2l };
        size_t ns[7] = { (size_t)ROWS * DMODEL, (size_t)QLEN * DMODEL,
                         (size_t)D3 * DMODEL, (size_t)DMODEL * DMODEL,
                         (size_t)DMODEL * DMODEL, (size_t)DFF * DMODEL,
                         (size_t)DMODEL * DFF };
        int base = 0;
        for (int s = 0; s < 7; s++) {
            sa.d[s].x = (const float4*)xs[s];
            sa.d[s].h = (uint2*)hs[s];
            sa.d[s].l = (uint2*)ls[s];
            sa.d[s].base = base;
            sa.d[s].pad = 0;
            base += (int)(ns[s] / 4);
        }
        split_all<<<(base + 255) / 256, 256>>>(sa, base);
    }

    const dim3 blk(256);
    gemm_tc<false, false, false, true><<<dim3(D3 / TN, ROWS / TM), blk, GEMM_SMEM>>>(
        wh, wl, qwh, qwl, nullptr, nullptr, hh, hl, D3, DMODEL);
    gemm_tc<false, false, false, true><<<dim3(DMODEL / TN, QLEN / TM), blk, GEMM_SMEM>>>(
        rh, rl, rwh, rwl, nullptr, nullptr, rkh, rkl, DMODEL, DMODEL);

    flash_attn<<<dim3(16, 64), dim3(256), FLASH_SMEM>>>(
        hh, hl, rkh, rkl, r_w_bias, r_r_bias, avh, avl);

    gemm_tc<false, false, true, false><<<dim3(DMODEL / TN, ROWS / TM), blk, GEMM_SMEM>>>(
        avh, avl, owh, owl, nullptr, tmp, nullptr, nullptr, DMODEL, DMODEL);

    add_ln<true><<<ROWS / 2, 512>>>(w, tmp, ln1_g, ln1_b, out1, o1h, o1l);

    gemm_tc<true, true, false, true><<<dim3(DFF / TN, ROWS / TM), blk, GEMM_SMEM>>>(
        o1h, o1l, f1h, f1l, ff_b1, nullptr, ff1h, ff1l, DFF, DMODEL);

    gemm_tc<true, false, true, false><<<dim3(DMODEL / TN, ROWS / TM), blk, GEMM_SMEM>>>(
        ff1h, ff1l, f2h, f2l, ff_b2, tmp, nullptr, nullptr, DMODEL, DFF);

    add_ln<false><<<ROWS / 2, 512>>>(out1, tmp, ln2_g, ln2_b, out, nullptr, nullptr);
}

// round 15
// speedup vs baseline: 1.0494x; 1.0494x over previous
#include <cuda_runtime.h>
#include <cuda_bf16.h>
#include <math.h>
#include <stdint.h>

#define QLEN   1024
#define DMODEL 1024
#define DFF    4096
#define ROWS   4096
#define D3     3072

typedef __nv_bfloat16 bf16;

__device__ float g_tmp[(size_t)ROWS * DMODEL];
__device__ float g_out1[(size_t)ROWS * DMODEL];

__device__ bf16 g_wh[(size_t)ROWS * DMODEL],   g_wl[(size_t)ROWS * DMODEL];
__device__ bf16 g_rh[(size_t)QLEN * DMODEL],   g_rl[(size_t)QLEN * DMODEL];
__device__ bf16 g_qwh[(size_t)D3 * DMODEL],    g_qwl[(size_t)D3 * DMODEL];
__device__ bf16 g_rwh[(size_t)DMODEL * DMODEL],g_rwl[(size_t)DMODEL * DMODEL];
__device__ bf16 g_owh[(size_t)DMODEL * DMODEL],g_owl[(size_t)DMODEL * DMODEL];
__device__ bf16 g_f1h[(size_t)DFF * DMODEL],   g_f1l[(size_t)DFF * DMODEL];
__device__ bf16 g_f2h[(size_t)DMODEL * DFF],   g_f2l[(size_t)DMODEL * DFF];
__device__ bf16 g_hh[(size_t)ROWS * D3],       g_hl[(size_t)ROWS * D3];
__device__ bf16 g_rkh[(size_t)QLEN * DMODEL],  g_rkl[(size_t)QLEN * DMODEL];
__device__ bf16 g_avh[(size_t)ROWS * DMODEL],  g_avl[(size_t)ROWS * DMODEL];
__device__ bf16 g_o1h[(size_t)ROWS * DMODEL],  g_o1l[(size_t)ROWS * DMODEL];
__device__ bf16 g_ff1h[(size_t)ROWS * DFF],    g_ff1l[(size_t)ROWS * DFF];

__device__ __forceinline__ uint32_t cvta_smem(const void* p) {
    uint32_t a;
    asm("{ .reg .u64 t; cvta.to.shared.u64 t, %1; cvt.u32.u64 %0, t; }"
        : "=r"(a) : "l"(p));
    return a;
}
#define SWZ(o) ((o) ^ (((o) >> 3) & 0x70))

__device__ __forceinline__ void cp16(uint32_t dst, const void* src) {
    asm volatile("cp.async.cg.shared.global [%0], [%1], 16;" :: "r"(dst), "l"(src));
}
__device__ __forceinline__ void cp16z(uint32_t dst, const void* src, uint32_t sz) {
    asm volatile("cp.async.cg.shared.global [%0], [%1], 16, %2;"
                 :: "r"(dst), "l"(src), "r"(sz));
}
__device__ __forceinline__ void cp_commit() {
    asm volatile("cp.async.commit_group;" ::: "memory");
}
template <int N> __device__ __forceinline__ void cp_wait() {
    asm volatile("cp.async.wait_group %0;" :: "n"(N) : "memory");
}
__device__ __forceinline__ void bar_pair(int id) {
    asm volatile("bar.sync %0, 64;" :: "r"(id) : "memory");
}
__device__ __forceinline__ void ldsm_x4(uint32_t& r0, uint32_t& r1,
                                        uint32_t& r2, uint32_t& r3, uint32_t a) {
    asm volatile("ldmatrix.sync.aligned.m8n8.x4.shared.b16 {%0,%1,%2,%3}, [%4];"
                 : "=r"(r0), "=r"(r1), "=r"(r2), "=r"(r3) : "r"(a));
}
__device__ __forceinline__ void ldsm_x2(uint32_t& r0, uint32_t& r1, uint32_t a) {
    asm volatile("ldmatrix.sync.aligned.m8n8.x2.shared.b16 {%0,%1}, [%2];"
                 : "=r"(r0), "=r"(r1) : "r"(a));
}
__device__ __forceinline__ void ldsm_x2t(uint32_t& r0, uint32_t& r1, uint32_t a) {
    asm volatile("ldmatrix.sync.aligned.m8n8.x2.trans.shared.b16 {%0,%1}, [%2];"
                 : "=r"(r0), "=r"(r1) : "r"(a));
}
__device__ __forceinline__ void mma_bf16(float* c, uint32_t a0, uint32_t a1,
                                         uint32_t a2, uint32_t a3,
                                         uint32_t b0, uint32_t b1) {
    asm volatile(
        "mma.sync.aligned.m16n8k16.row.col.f32.bf16.bf16.f32 "
        "{%0,%1,%2,%3}, {%4,%5,%6,%7}, {%8,%9}, {%0,%1,%2,%3};"
        : "+f"(c[0]), "+f"(c[1]), "+f"(c[2]), "+f"(c[3])
        : "r"(a0), "r"(a1), "r"(a2), "r"(a3), "r"(b0), "r"(b1));
}
__device__ __forceinline__ void split2(float x, float y, uint32_t& h, uint32_t& l) {
    bf16 hx = __float2bfloat16_rn(x), hy = __float2bfloat16_rn(y);
    bf16 lx = __float2bfloat16_rn(x - __bfloat162float(hx));
    bf16 ly = __float2bfloat16_rn(y - __bfloat162float(hy));
    __nv_bfloat162 hp; hp.x = hx; hp.y = hy;
    __nv_bfloat162 lp; lp.x = lx; lp.y = ly;
    h = *(uint32_t*)&hp; l = *(uint32_t*)&lp;
}

// ---------------- dense GEMM v2 body (R12 verified config) -----------------
#define TM 128
#define TN 128
#define KC 64
#define STAGES 3
#define GT 256
#define ARR16   16384
#define STGSZ   (4 * ARR16)
#define SM_S    1024
#define GEMM_SMEM (SM_S + STAGES * STGSZ)

template <bool BIAS, bool RELU, bool OUTF, bool OUTS>
__device__ __forceinline__ void gemm_body(
    const bf16* __restrict__ Ah, const bf16* __restrict__ Al,
    const bf16* __restrict__ Bh, const bf16* __restrict__ Bl,
    const float* __restrict__ bias, float* __restrict__ C,
    bf16* __restrict__ Ch, bf16* __restrict__ Cl, int N, int K,
    int i0, int j0, char* smem)
{
    const uint32_t sbase = cvta_smem(smem);
    const int tid  = threadIdx.x;
    const int lane = tid & 31;
    const int warp = tid >> 5;
    const int wm   = warp >> 2, wn = warp & 3;

    if (BIAS) { if (tid < TN) ((float*)smem)[tid] = bias[j0 + tid]; }

    const int NC = K / KC;
    const bf16* srcs[4] = { Ah + (size_t)i0 * K, Al + (size_t)i0 * K,
                            Bh + (size_t)j0 * K, Bl + (size_t)j0 * K };

    auto load_chunk = [&](int c) {
        const uint32_t stb = sbase + SM_S + (c % STAGES) * STGSZ;
        const int kc = c * KC;
#pragma unroll
        for (int it = 0; it < 16; it++) {
            int s = tid + it * GT;
            int arr = s >> 10, sect = s & 1023;
            int row = sect >> 3, sc = sect & 7;
            cp16(stb + arr * ARR16 + SWZ(row * 128 + sc * 16),
                 (const char*)(srcs[arr] + (size_t)row * K + kc) + sc * 16);
        }
    };

    float acc[4][4][4];
#pragma unroll
    for (int mt = 0; mt < 4; mt++)
#pragma unroll
        for (int nt = 0; nt < 4; nt++)
#pragma unroll
            for (int e = 0; e < 4; e++) acc[mt][nt][e] = 0.0f;

#pragma unroll
    for (int c = 0; c < STAGES - 1; c++) { load_chunk(c); cp_commit(); }

    const int a_row = wm * 64 + (lane & 15);
    const int a_ko  = (lane >> 4) * 16;
    const int b_row = wn * 32 + (lane & 7);
    const int b_ko  = ((lane >> 3) & 1) * 16;

    for (int c = 0; c < NC; c++) {
        const int cl = c + STAGES - 1;
        if (cl < NC) load_chunk(cl);
        cp_commit();
        cp_wait<STAGES - 1>();
        __syncthreads();
        const uint32_t stb = sbase + SM_S + (c % STAGES) * STGSZ;
#pragma unroll
        for (int ks = 0; ks < 4; ks++) {
            uint32_t bh[4][2], bl[4][2];
#pragma unroll
            for (int nt = 0; nt < 4; nt++) {
                uint32_t off = SWZ((b_row + nt * 8) * 128 + ks * 32 + b_ko);
                ldsm_x2(bh[nt][0], bh[nt][1], stb + 2 * ARR16 + off);
                ldsm_x2(bl[nt][0], bl[nt][1], stb + 3 * ARR16 + off);
            }
#pragma unroll
            for (int mt = 0; mt < 4; mt++) {
                uint32_t off = SWZ((a_row + mt * 16) * 128 + ks * 32 + a_ko);
                uint32_t ah0, ah1, ah2, ah3, al0, al1, al2, al3;
                ldsm_x4(ah0, ah1, ah2, ah3, stb + off);
                ldsm_x4(al0, al1, al2, al3, stb + ARR16 + off);
#pragma unroll
                for (int nt = 0; nt < 4; nt++) {
                    mma_bf16(acc[mt][nt], ah0, ah1, ah2, ah3, bh[nt][0], bh[nt][1]);
                    mma_bf16(acc[mt][nt], ah0, ah1, ah2, ah3, bl[nt][0], bl[nt][1]);
                    mma_bf16(acc[mt][nt], al0, al1, al2, al3, bh[nt][0], bh[nt][1]);
                }
            }
        }
        __syncthreads();
    }

    const int er = lane >> 2, ec = (lane & 3) * 2;
#pragma unroll
    for (int mt = 0; mt < 4; mt++) {
#pragma unroll
        for (int nt = 0; nt < 4; nt++) {
            const int col = wn * 32 + nt * 8 + ec;
            float b0 = 0.0f, b1 = 0.0f;
            if (BIAS) { b0 = ((float*)smem)[col]; b1 = ((float*)smem)[col + 1]; }
#pragma unroll
            for (int h = 0; h < 2; h++) {
                const int row = i0 + wm * 64 + mt * 16 + er + h * 8;
                float v0 = acc[mt][nt][2 * h] + b0;
                float v1 = acc[mt][nt][2 * h + 1] + b1;
                if (RELU) { v0 = fmaxf(v0, 0.0f); v1 = fmaxf(v1, 0.0f); }
                if (OUTF)
                    *(float2*)(C + (size_t)row * N + j0 + col) = make_float2(v0, v1);
                if (OUTS) {
                    uint32_t hh, ll;
                    split2(v0, v1, hh, ll);
                    *(uint32_t*)(Ch + (size_t)row * N + j0 + col) = hh;
                    *(uint32_t*)(Cl + (size_t)row * N + j0 + col) = ll;
                }
            }
        }
    }
}

template <bool BIAS, bool RELU, bool OUTF, bool OUTS>
__global__ __launch_bounds__(GT) void gemm_tc(
    const bf16* __restrict__ Ah, const bf16* __restrict__ Al,
    const bf16* __restrict__ Bh, const bf16* __restrict__ Bl,
    const float* __restrict__ bias, float* __restrict__ C,
    bf16* __restrict__ Ch, bf16* __restrict__ Cl, int N, int K)
{
    extern __shared__ char smem[];
    gemm_body<BIAS, RELU, OUTF, OUTS>(Ah, Al, Bh, Bl, bias, C, Ch, Cl, N, K,
                                      blockIdx.y * TM, blockIdx.x * TN, smem);
}

// merged QKV + rk launch (both OUTS-only, K=1024); QKV blocks first
#define QKV_BX (D3 / TN)            // 24
#define QKV_BLKS (QKV_BX * (ROWS / TM))  // 768
#define RK_BX (DMODEL / TN)         // 8
#define TOT_BLKS (QKV_BLKS + RK_BX * (QLEN / TM))  // 832

__global__ __launch_bounds__(GT) void gemm_qkv_rk(
    const bf16* __restrict__ wh, const bf16* __restrict__ wl,
    const bf16* __restrict__ qwh, const bf16* __restrict__ qwl,
    bf16* __restrict__ hh, bf16* __restrict__ hl,
    const bf16* __restrict__ rh, const bf16* __restrict__ rl,
    const bf16* __restrict__ rwh, const bf16* __restrict__ rwl,
    bf16* __restrict__ rkh, bf16* __restrict__ rkl)
{
    extern __shared__ char smem[];
    const int bid = blockIdx.x;
    if (bid < QKV_BLKS) {
        gemm_body<false, false, false, true>(
            wh, wl, qwh, qwl, nullptr, nullptr, hh, hl, D3, DMODEL,
            (bid / QKV_BX) * TM, (bid % QKV_BX) * TN, smem);
    } else {
        const int b2 = bid - QKV_BLKS;
        gemm_body<false, false, false, true>(
            rh, rl, rwh, rwl, nullptr, nullptr, rkh, rkl, DMODEL, DMODEL,
            (b2 / RK_BX) * TM, (b2 % RK_BX) * TN, smem);
    }
}

// -------- batched split: all 7 tensors, descriptors passed BY VALUE --------
struct SplitDesc { const float4* x; uint2* h; uint2* l; int base; int pad; };
struct SplitArgs { SplitDesc d[7]; };

__global__ __launch_bounds__(256) void split_all(SplitArgs args, int total4)
{
    int i = blockIdx.x * 256 + threadIdx.x;
    if (i >= total4) return;
    int seg = 0;
#pragma unroll
    for (int s = 1; s < 7; s++) if (i >= args.d[s].base) seg = s;
    int k = i - args.d[seg].base;
    float4 v = args.d[seg].x[k];
    uint32_t h01, l01, h23, l23;
    split2(v.x, v.y, h01, l01);
    split2(v.z, v.w, h23, l23);
    args.d[seg].h[k] = make_uint2(h01, h23);
    args.d[seg].l[k] = make_uint2(l01, l23);
}

// ------------------------- fused flash attention (R8) ----------------------
#define FQWH 0
#define FQWL 8192
#define FQRH 16384
#define FQRL 24576
#define FKV  32768
#define FRK  98304
#define FDT  163840
#define FSTM 197632
#define FSTS 198144
#define FLASH_SMEM 198656

__global__ __launch_bounds__(256) void flash_attn(
    const bf16* __restrict__ hh, const bf16* __restrict__ hl,
    const bf16* __restrict__ rkh, const bf16* __restrict__ rkl,
    const float* __restrict__ rwb, const float* __restrict__ rrb,
    bf16* __restrict__ avh, bf16* __restrict__ avl)
{
    extern __shared__ char sm[];
    const uint32_t sb = cvta_smem(sm);
    const int tid = threadIdx.x, lane = tid & 31, w = tid >> 5;
    const int wr = w >> 1, wc = w & 1;
    const int ib = 15 - (int)blockIdx.x;
    const int bn = blockIdx.y, b = bn >> 4, n = bn & 15;
    const int i0 = ib * 64;
    const int tw0 = QLEN - 64 - i0;
    const int ntiles = ib + 1;
    const size_t bq = (size_t)b * QLEN;
    const int barid = wr + 1;

    auto load_kv = [&](int jt) {
        const uint32_t dstb = sb + FKV + (jt & 1) * 32768;
#pragma unroll
        for (int it = 0; it < 8; it++) {
            int s = tid + it * 256;
            int arr = s >> 9, sect = s & 511;
            int row = sect >> 3, sc = sect & 7;
            const bf16* src = ((arr & 1) ? hl : hh) +
                (bq + jt * 64 + row) * D3 + ((arr >> 1) + 1) * DMODEL + n * 64;
            cp16(dstb + arr * 8192 + SWZ(row * 128 + sc * 16),
                 (const char*)src + sc * 16);
        }
    };
    auto load_rk = [&](int tile) {
        const uint32_t dstb = sb + FRK + (tile & 3) * 16384;
#pragma unroll
        for (int it = 0; it < 4; it++) {
            int s = tid + it * 256;
            int arr = s >> 9, sect = s & 511;
            int row = sect >> 3, sc = sect & 7;
            int t = tw0 + tile * 64 + row;
            int tc = (t < QLEN) ? t : 0;
            const bf16* src = (arr ? rkl : rkh) + (size_t)tc * DMODEL + n * 64;
            cp16z(dstb + arr * 8192 + SWZ(row * 128 + sc * 16),
                  (const char*)src + sc * 16, (t < QLEN) ? 16u : 0u);
        }
    };

    load_kv(0); load_rk(0); load_rk(1); cp_commit();

#pragma unroll
    for (int it = 0; it < 4; it++) {
        int s = tid + it * 256;
        int row = s >> 4, c4 = (s & 15) << 2;
        const size_t qoff = (bq + i0 + row) * D3 + n * 64 + c4;
        uint2 qh = *(const uint2*)(hh + qoff);
        uint2 ql = *(const uint2*)(hl + qoff);
        __nv_bfloat162 h01 = *(__nv_bfloat162*)&qh.x, h23 = *(__nv_bfloat162*)&qh.y;
        __nv_bfloat162 l01 = *(__nv_bfloat162*)&ql.x, l23 = *(__nv_bfloat162*)&ql.y;
        float q0 = __bfloat162float(h01.x) + __bfloat162float(l01.x);
        float q1 = __bfloat162float(h01.y) + __bfloat162float(l01.y);
        float q2 = __bfloat162float(h23.x) + __bfloat162float(l23.x);
        float q3 = __bfloat162float(h23.y) + __bfloat162float(l23.y);
        float4 bw = *(const float4*)(rwb + n * 64 + c4);
        float4 br = *(const float4*)(rrb + n * 64 + c4);
        uint32_t a01, b01, a23, b23;
        uint32_t off = SWZ(row * 128 + c4 * 2);
        split2((q0 + bw.x) * 0.125f, (q1 + bw.y) * 0.125f, a01, b01);
        split2((q2 + bw.z) * 0.125f, (q3 + bw.w) * 0.125f, a23, b23);
        *(uint2*)(sm + FQWH + off) = make_uint2(a01, a23);
        *(uint2*)(sm + FQWL + off) = make_uint2(b01, b23);
        split2((q0 + br.x) * 0.125f, (q1 + br.y) * 0.125f, a01, b01);
        split2((q2 + br.z) * 0.125f, (q3 + br.w) * 0.125f, a23, b23);
        *(uint2*)(sm + FQRH + off) = make_uint2(a01, a23);
        *(uint2*)(sm + FQRL + off) = make_uint2(b01, b23);
    }

    float m0 = -INFINITY, m1 = -INFINITY, l0 = 0.0f, l1 = 0.0f;
    float accO[8][4];
#pragma unroll
    for (int nt = 0; nt < 8; nt++)
#pragma unroll
        for (int e = 0; e < 4; e++) accO[nt][e] = 0.0f;

    const int r0 = lane >> 2, c00 = (lane & 3) * 2;
    const uint32_t aoff = (wr * 16 + (lane & 15)) * 128 + ((lane >> 4) << 4);
    const uint32_t bko  = ((lane >> 3) & 1) << 4;
    const int u0 = 6 - 2 * wr;
    float* dwp = (float*)(sm + FDT + wr * 8448);
    float* stM = (float*)(sm + FSTM);
    float* stS = (float*)(sm + FSTS);

    for (int jt = 0; jt < ntiles; jt++) {
        cp_wait<0>();
        __syncthreads();
        if (jt + 1 < ntiles) { load_kv(jt + 1); load_rk(jt + 2); }
        cp_commit();

        const uint32_t kvb = sb + FKV + (jt & 1) * 32768;
        float aS[4][4];
#pragma unroll
        for (int nt = 0; nt < 4; nt++)
#pragma unroll
            for (int e = 0; e < 4; e++) aS[nt][e] = 0.0f;
#pragma unroll
        for (int kc = 0; kc < 4; kc++) {
            uint32_t ah0, ah1, ah2, ah3, al0, al1, al2, al3;
            ldsm_x4(ah0, ah1, ah2, ah3, sb + FQWH + SWZ(aoff + kc * 32));
            ldsm_x4(al0, al1, al2, al3, sb + FQWL + SWZ(aoff + kc * 32));
#pragma unroll
            for (int nt = 0; nt < 4; nt++) {
                uint32_t boff = (wc * 32 + nt * 8 + (lane & 7)) * 128 + kc * 32 + bko;
                uint32_t b0, b1;
                ldsm_x2(b0, b1, kvb + SWZ(boff));
                mma_bf16(aS[nt], ah0, ah1, ah2, ah3, b0, b1);
                mma_bf16(aS[nt], al0, al1, al2, al3, b0, b1);
                ldsm_x2(b0, b1, kvb + 8192 + SWZ(boff));
                mma_bf16(aS[nt], ah0, ah1, ah2, ah3, b0, b1);
            }
        }

        float aB[5][4];
#pragma unroll
        for (int v = 0; v < 5; v++)
#pragma unroll
            for (int e = 0; e < 4; e++) aB[v][e] = 0.0f;
#pragma unroll
        for (int kc = 0; kc < 4; kc++) {
            uint32_t ah0, ah1, ah2, ah3, al0, al1, al2, al3;
            ldsm_x4(ah0, ah1, ah2, ah3, sb + FQRH + SWZ(aoff + kc * 32));
            ldsm_x4(al0, al1, al2, al3, sb + FQRL + SWZ(aoff + kc * 32));
#pragma unroll
            for (int v = 0; v < 5; v++) {
                int cu = u0 + wc * 5 + v;
                uint32_t rbase = sb + FRK + ((jt + (cu >> 3)) & 3) * 16384;
                uint32_t boff = ((cu & 7) * 8 + (lane & 7)) * 128 + kc * 32 + bko;
                uint32_t b0, b1;
                ldsm_x2(b0, b1, rbase + SWZ(boff));
                mma_bf16(aB[v], ah0, ah1, ah2, ah3, b0, b1);
                mma_bf16(aB[v], al0, al1, al2, al3, b0, b1);
                ldsm_x2(b0, b1, rbase + 8192 + SWZ(boff));
                mma_bf16(aB[v], ah0, ah1, ah2, ah3, b0, b1);
            }
        }
#pragma unroll
        for (int v = 0; v < 5; v++) {
            int col = (u0 + wc * 5 + v) * 8 + c00;
            dwp[r0 * 132 + col]           = aB[v][0];
            dwp[r0 * 132 + col + 1]       = aB[v][1];
            dwp[(r0 + 8) * 132 + col]     = aB[v][2];
            dwp[(r0 + 8) * 132 + col + 1] = aB[v][3];
        }
        bar_pair(barid);

        const int s0 = 63 - wr * 16 - r0, s1 = s0 - 8;
        const int gi0 = i0 + wr * 16 + r0, gi1 = gi0 + 8;
        const int j0 = jt * 64;
        float tm0 = -INFINITY, tm1 = -INFINITY;
#pragma unroll
        for (int nt = 0; nt < 4; nt++) {
            int cb = wc * 32 + nt * 8 + c00;
            float v0 = aS[nt][0] + dwp[r0 * 132 + cb + s0];
            float v1 = aS[nt][1] + dwp[r0 * 132 + cb + 1 + s0];
            float v2 = aS[nt][2] + dwp[(r0 + 8) * 132 + cb + s1];
            float v3 = aS[nt][3] + dwp[(r0 + 8) * 132 + cb + 1 + s1];
            if (j0 + cb     > gi0) v0 = -INFINITY;
            if (j0 + cb + 1 > gi0) v1 = -INFINITY;
            if (j0 + cb     > gi1) v2 = -INFINITY;
            if (j0 + cb + 1 > gi1) v3 = -INFINITY;
            aS[nt][0] = v0; aS[nt][1] = v1; aS[nt][2] = v2; aS[nt][3] = v3;
            tm0 = fmaxf(tm0, fmaxf(v0, v1));
            tm1 = fmaxf(tm1, fmaxf(v2, v3));
        }
        tm0 = fmaxf(tm0, __shfl_xor_sync(0xffffffffu, tm0, 1));
        tm0 = fmaxf(tm0, __shfl_xor_sync(0xffffffffu, tm0, 2));
        tm1 = fmaxf(tm1, __shfl_xor_sync(0xffffffffu, tm1, 1));
        tm1 = fmaxf(tm1, __shfl_xor_sync(0xffffffffu, tm1, 2));
        if ((lane & 3) == 0) {
            stM[(wr * 16 + r0) * 2 + wc]     = tm0;
            stM[(wr * 16 + r0 + 8) * 2 + wc] = tm1;
        }
        bar_pair(barid);
        float cm0 = fmaxf(stM[(wr * 16 + r0) * 2],     stM[(wr * 16 + r0) * 2 + 1]);
        float cm1 = fmaxf(stM[(wr * 16 + r0 + 8) * 2], stM[(wr * 16 + r0 + 8) * 2 + 1]);
        float mn0 = fmaxf(m0, cm0), mn1 = fmaxf(m1, cm1);
        float sc0 = __expf(m0 - mn0), sc1 = __expf(m1 - mn1);
        m0 = mn0; m1 = mn1;
        float ts0 = 0.0f, ts1 = 0.0f;
#pragma unroll
        for (int nt = 0; nt < 4; nt++) {
            float p0 = __expf(aS[nt][0] - m0);
            float p1 = __expf(aS[nt][1] - m0);
            float p2 = __expf(aS[nt][2] - m1);
            float p3 = __expf(aS[nt][3] - m1);
            aS[nt][0] = p0; aS[nt][1] = p1; aS[nt][2] = p2; aS[nt][3] = p3;
            ts0 += p0 + p1; ts1 += p2 + p3;
        }
        ts0 += __shfl_xor_sync(0xffffffffu, ts0, 1);
        ts0 += __shfl_xor_sync(0xffffffffu, ts0, 2);
        ts1 += __shfl_xor_sync(0xffffffffu, ts1, 1);
        ts1 += __shfl_xor_sync(0xffffffffu, ts1, 2);
        if ((lane & 3) == 0) {
            stS[(wr * 16 + r0) * 2 + wc]     = ts0;
            stS[(wr * 16 + r0 + 8) * 2 + wc] = ts1;
        }
        bar_pair(barid);
        float cs0 = stS[(wr * 16 + r0) * 2]     + stS[(wr * 16 + r0) * 2 + 1];
        float cs1 = stS[(wr * 16 + r0 + 8) * 2] + stS[(wr * 16 + r0 + 8) * 2 + 1];
        l0 = l0 * sc0 + cs0;
        l1 = l1 * sc1 + cs1;
#pragma unroll
        for (int nt = 0; nt < 8; nt++) {
            accO[nt][0] *= sc0; accO[nt][1] *= sc0;
            accO[nt][2] *= sc1; accO[nt][3] *= sc1;
        }

        uint32_t ph[2][4], pl[2][4];
#pragma unroll
        for (int kcl = 0; kcl < 2; kcl++) {
            split2(aS[2*kcl][0],   aS[2*kcl][1],   ph[kcl][0], pl[kcl][0]);
            split2(aS[2*kcl][2],   aS[2*kcl][3],   ph[kcl][1], pl[kcl][1]);
            split2(aS[2*kcl+1][0], aS[2*kcl+1][1], ph[kcl][2], pl[kcl][2]);
            split2(aS[2*kcl+1][2], aS[2*kcl+1][3], ph[kcl][3], pl[kcl][3]);
        }
#pragma unroll
        for (int kcl = 0; kcl < 2; kcl++) {
            uint32_t voff = (wc * 32 + kcl * 16 + (lane & 15)) * 128;
#pragma unroll
            for (int vnt = 0; vnt < 8; vnt++) {
                uint32_t b0, b1;
                ldsm_x2t(b0, b1, kvb + 16384 + SWZ(voff + vnt * 16));
                mma_bf16(accO[vnt], ph[kcl][0], ph[kcl][1], ph[kcl][2], ph[kcl][3], b0, b1);
                mma_bf16(accO[vnt], pl[kcl][0], pl[kcl][1], pl[kcl][2], pl[kcl][3], b0, b1);
                ldsm_x2t(b0, b1, kvb + 24576 + SWZ(voff + vnt * 16));
                mma_bf16(accO[vnt], ph[kcl][0], ph[kcl][1], ph[kcl][2], ph[kcl][3], b0, b1);
            }
        }
    }

    float* red = (float*)(sm + FDT + wr * 4096);
    if (wc == 1) {
#pragma unroll
        for (int nt = 0; nt < 8; nt++)
#pragma unroll
            for (int e = 0; e < 4; e++)
                red[(nt * 4 + e) * 32 + lane] = accO[nt][e];
    }
    __syncthreads();
    if (wc == 0) {
#pragma unroll
        for (int nt = 0; nt < 8; nt++)
#pragma unroll
            for (int e = 0; e < 4; e++)
                accO[nt][e] += red[(nt * 4 + e) * 32 + lane];
        const float inv0 = 1.0f / l0, inv1 = 1.0f / l1;
        const size_t row0 = (bq + i0 + wr * 16 + r0) * DMODEL + n * 64;
        const size_t row1 = row0 + 8 * DMODEL;
#pragma unroll
        for (int nt = 0; nt < 8; nt++) {
            int col = nt * 8 + c00;
            uint32_t hh2, ll2;
            split2(accO[nt][0] * inv0, accO[nt][1] * inv0, hh2, ll2);
            *(uint32_t*)(avh + row0 + col) = hh2;
            *(uint32_t*)(avl + row0 + col) = ll2;
            split2(accO[nt][2] * inv1, accO[nt][3] * inv1, hh2, ll2);
            *(uint32_t*)(avh + row1 + col) = hh2;
            *(uint32_t*)(avl + row1 + col) = ll2;
        }
    }
}

// ------------------------- residual + LayerNorm (2 rows/CTA) ---------------
template <bool SPLIT>
__global__ __launch_bounds__(512) void add_ln(
    const float* __restrict__ a, const float* __restrict__ bb,
    const float* __restrict__ gamma, const float* __restrict__ beta,
    float* __restrict__ out, bf16* __restrict__ oh, bf16* __restrict__ ol)
{
    const int row = blockIdx.x * 2 + (threadIdx.x >> 8);
    const size_t base = (size_t)row * DMODEL;
    const int tid = threadIdx.x & 255;
    const int half = threadIdx.x >> 8;
    __shared__ float red[2][8];

    float x[4];
    float sum = 0.0f;
#pragma unroll
    for (int c = 0; c < 4; c++) {
        int j = tid + (c << 8);
        x[c] = a[base + j] + bb[base + j];
        sum += x[c];
    }
#pragma unroll
    for (int o = 16; o; o >>= 1) sum += __shfl_xor_sync(0xffffffffu, sum, o);
    if ((tid & 31) == 0) red[half][tid >> 5] = sum;
    __syncthreads();
    float tot = red[half][0];
#pragma unroll
    for (int w = 1; w < 8; w++) tot += red[half][w];
    __syncthreads();
    const float mean = tot * (1.0f / DMODEL);

    float vs = 0.0f;
#pragma unroll
    for (int c = 0; c < 4; c++) { float d = x[c] - mean; vs += d * d; }
#pragma unroll
    for (int o = 16; o; o >>= 1) vs += __shfl_xor_sync(0xffffffffu, vs, o);
    if ((tid & 31) == 0) red[half][tid >> 5] = vs;
    __syncthreads();
    float vtot = red[half][0];
#pragma unroll
    for (int w = 1; w < 8; w++) vtot += red[half][w];
    const float rstd = rsqrtf(vtot * (1.0f / DMODEL) + 1e-5f);

#pragma unroll
    for (int c = 0; c < 4; c++) {
        int j = tid + (c << 8);
        float y = (x[c] - mean) * rstd * gamma[j] + beta[j];
        out[base + j] = y;
        if (SPLIT) {
            bf16 h = __float2bfloat16_rn(y);
            bf16 l = __float2bfloat16_rn(y - __bfloat162float(h));
            oh[base + j] = h; ol[base + j] = l;
        }
    }
}

// ------------------------------- launcher ----------------------------------
extern "C" void kernel_launch(void* const* d_in, const int* in_sizes, int n_in,
                              void* d_out, int out_size)
{
    (void)in_sizes; (void)n_in; (void)out_size;

    const float* w        = (const float*)d_in[0];
    const float* r        = (const float*)d_in[1];
    const float* qkv_w    = (const float*)d_in[3];
    const float* r_w      = (const float*)d_in[4];
    const float* o_w      = (const float*)d_in[5];
    const float* r_w_bias = (const float*)d_in[6];
    const float* r_r_bias = (const float*)d_in[7];
    const float* ln1_g    = (const float*)d_in[8];
    const float* ln1_b    = (const float*)d_in[9];
    const float* ff_w1    = (const float*)d_in[10];
    const float* ff_b1    = (const float*)d_in[11];
    const float* ff_w2    = (const float*)d_in[12];
    const float* ff_b2    = (const float*)d_in[13];
    const float* ln2_g    = (const float*)d_in[14];
    const float* ln2_b    = (const float*)d_in[15];
    float* out = (float*)d_out;

    float *tmp, *out1;
    cudaGetSymbolAddress((void**)&tmp,  g_tmp);
    cudaGetSymbolAddress((void**)&out1, g_out1);

    bf16 *wh, *wl, *rh, *rl, *qwh, *qwl, *rwh, *rwl, *owh, *owl;
    bf16 *f1h, *f1l, *f2h, *f2l, *avh, *avl, *o1h, *o1l, *ff1h, *ff1l;
    bf16 *hh, *hl, *rkh, *rkl;
    cudaGetSymbolAddress((void**)&wh,  g_wh);  cudaGetSymbolAddress((void**)&wl,  g_wl);
    cudaGetSymbolAddress((void**)&rh,  g_rh);  cudaGetSymbolAddress((void**)&rl,  g_rl);
    cudaGetSymbolAddress((void**)&qwh, g_qwh); cudaGetSymbolAddress((void**)&qwl, g_qwl);
    cudaGetSymbolAddress((void**)&rwh, g_rwh); cudaGetSymbolAddress((void**)&rwl, g_rwl);
    cudaGetSymbolAddress((void**)&owh, g_owh); cudaGetSymbolAddress((void**)&owl, g_owl);
    cudaGetSymbolAddress((void**)&f1h, g_f1h); cudaGetSymbolAddress((void**)&f1l, g_f1l);
    cudaGetSymbolAddress((void**)&f2h, g_f2h); cudaGetSymbolAddress((void**)&f2l, g_f2l);
    cudaGetSymbolAddress((void**)&avh, g_avh); cudaGetSymbolAddress((void**)&avl, g_avl);
    cudaGetSymbolAddress((void**)&o1h, g_o1h); cudaGetSymbolAddress((void**)&o1l, g_o1l);
    cudaGetSymbolAddress((void**)&ff1h, g_ff1h); cudaGetSymbolAddress((void**)&ff1l, g_ff1l);
    cudaGetSymbolAddress((void**)&hh,  g_hh);  cudaGetSymbolAddress((void**)&hl,  g_hl);
    cudaGetSymbolAddress((void**)&rkh, g_rkh); cudaGetSymbolAddress((void**)&rkl, g_rkl);

    cudaFuncSetAttribute(gemm_qkv_rk,
                         cudaFuncAttributeMaxDynamicSharedMemorySize, GEMM_SMEM);
    cudaFuncSetAttribute(gemm_tc<false, false, true, false>,
                         cudaFuncAttributeMaxDynamicSharedMemorySize, GEMM_SMEM);
    cudaFuncSetAttribute(gemm_tc<true, true, false, true>,
                         cudaFuncAttributeMaxDynamicSharedMemorySize, GEMM_SMEM);
    cudaFuncSetAttribute(gemm_tc<true, false, true, false>,
                         cudaFuncAttributeMaxDynamicSharedMemorySize, GEMM_SMEM);
    cudaFuncSetAttribute(flash_attn,
                         cudaFuncAttributeMaxDynamicSharedMemorySize, FLASH_SMEM);

    // one batched split launch; descriptors passed by value (graph-safe)
    {
        SplitArgs sa;
        const float* xs[7] = { w, r, qkv_w, r_w, o_w, ff_w1, ff_w2 };
        bf16* hs[7] = { wh, rh, qwh, rwh, owh, f1h, f2h };
        bf16* ls[7] = { wl, rl, qwl, rwl, owl, f1l, f2l };
        size_t ns[7] = { (size_t)ROWS * DMODEL, (size_t)QLEN * DMODEL,
                         (size_t)D3 * DMODEL, (size_t)DMODEL * DMODEL,
                         (size_t)DMODEL * DMODEL, (size_t)DFF * DMODEL,
                         (size_t)DMODEL * DFF };
        int base = 0;
        for (int s = 0; s < 7; s++) {
            sa.d[s].x = (const float4*)xs[s];
            sa.d[s].h = (uint2*)hs[s];
            sa.d[s].l = (uint2*)ls[s];
            sa.d[s].base = base;
            sa.d[s].pad = 0;
            base += (int)(ns[s] / 4);
        }
        split_all<<<(base + 255) / 256, 256>>>(sa, base);
    }

    const dim3 blk(256);
    // merged QKV + rk GEMM (fills QKV tail wave with rk blocks)
    gemm_qkv_rk<<<TOT_BLKS, blk, GEMM_SMEM>>>(
        wh, wl, qwh, qwl, hh, hl, rh, rl, rwh, rwl, rkh, rkl);

    flash_attn<<<dim3(16, 64), dim3(256), FLASH_SMEM>>>(
        hh, hl, rkh, rkl, r_w_bias, r_r_bias, avh, avl);

    gemm_tc<false, false, true, false><<<dim3(DMODEL / TN, ROWS / TM), blk, GEMM_SMEM>>>(
        avh, avl, owh, owl, nullptr, tmp, nullptr, nullptr, DMODEL, DMODEL);

    add_ln<true><<<ROWS / 2, 512>>>(w, tmp, ln1_g, ln1_b, out1, o1h, o1l);

    gemm_tc<true, true, false, true><<<dim3(DFF / TN, ROWS / TM), blk, GEMM_SMEM>>>(
        o1h, o1l, f1h, f1l, ff_b1, nullptr, ff1h, ff1l, DFF, DMODEL);

    gemm_tc<true, false, true, false><<<dim3(DMODEL / TN, ROWS / TM), blk, GEMM_SMEM>>>(
        ff1h, ff1l, f2h, f2l, ff_b2, tmp, nullptr, nullptr, DMODEL, DFF);

    add_ln<false><<<ROWS / 2, 512>>>(out1, tmp, ln2_g, ln2_b, out, nullptr, nullptr);
}

// round 16
// speedup vs baseline: 1.0810x; 1.0301x over previous
#include <cuda_runtime.h>
#include <cuda_bf16.h>
#include <math.h>
#include <stdint.h>

#define QLEN   1024
#define DMODEL 1024
#define DFF    4096
#define ROWS   4096
#define D3     3072

typedef __nv_bfloat16 bf16;

__device__ float g_tmp[(size_t)ROWS * DMODEL];
__device__ float g_out1[(size_t)ROWS * DMODEL];
__device__ float g_pt[(size_t)4 * ROWS * DMODEL];   // FF2 split-K partials

__device__ bf16 g_wh[(size_t)ROWS * DMODEL],   g_wl[(size_t)ROWS * DMODEL];
__device__ bf16 g_rh[(size_t)QLEN * DMODEL],   g_rl[(size_t)QLEN * DMODEL];
__device__ bf16 g_qwh[(size_t)D3 * DMODEL],    g_qwl[(size_t)D3 * DMODEL];
__device__ bf16 g_rwh[(size_t)DMODEL * DMODEL],g_rwl[(size_t)DMODEL * DMODEL];
__device__ bf16 g_owh[(size_t)DMODEL * DMODEL],g_owl[(size_t)DMODEL * DMODEL];
__device__ bf16 g_f1h[(size_t)DFF * DMODEL],   g_f1l[(size_t)DFF * DMODEL];
__device__ bf16 g_f2h[(size_t)DMODEL * DFF],   g_f2l[(size_t)DMODEL * DFF];
__device__ bf16 g_hh[(size_t)ROWS * D3],       g_hl[(size_t)ROWS * D3];
__device__ bf16 g_rkh[(size_t)QLEN * DMODEL],  g_rkl[(size_t)QLEN * DMODEL];
__device__ bf16 g_avh[(size_t)ROWS * DMODEL],  g_avl[(size_t)ROWS * DMODEL];
__device__ bf16 g_o1h[(size_t)ROWS * DMODEL],  g_o1l[(size_t)ROWS * DMODEL];
__device__ bf16 g_ff1h[(size_t)ROWS * DFF],    g_ff1l[(size_t)ROWS * DFF];

__device__ __forceinline__ uint32_t cvta_smem(const void* p) {
    uint32_t a;
    asm("{ .reg .u64 t; cvta.to.shared.u64 t, %1; cvt.u32.u64 %0, t; }"
        : "=r"(a) : "l"(p));
    return a;
}
#define SWZ(o) ((o) ^ (((o) >> 3) & 0x70))

__device__ __forceinline__ void cp16(uint32_t dst, const void* src) {
    asm volatile("cp.async.cg.shared.global [%0], [%1], 16;" :: "r"(dst), "l"(src));
}
__device__ __forceinline__ void cp16z(uint32_t dst, const void* src, uint32_t sz) {
    asm volatile("cp.async.cg.shared.global [%0], [%1], 16, %2;"
                 :: "r"(dst), "l"(src), "r"(sz));
}
__device__ __forceinline__ void cp_commit() {
    asm volatile("cp.async.commit_group;" ::: "memory");
}
template <int N> __device__ __forceinline__ void cp_wait() {
    asm volatile("cp.async.wait_group %0;" :: "n"(N) : "memory");
}
__device__ __forceinline__ void bar_pair(int id) {
    asm volatile("bar.sync %0, 64;" :: "r"(id) : "memory");
}
__device__ __forceinline__ void ldsm_x4(uint32_t& r0, uint32_t& r1,
                                        uint32_t& r2, uint32_t& r3, uint32_t a) {
    asm volatile("ldmatrix.sync.aligned.m8n8.x4.shared.b16 {%0,%1,%2,%3}, [%4];"
                 : "=r"(r0), "=r"(r1), "=r"(r2), "=r"(r3) : "r"(a));
}
__device__ __forceinline__ void ldsm_x2(uint32_t& r0, uint32_t& r1, uint32_t a) {
    asm volatile("ldmatrix.sync.aligned.m8n8.x2.shared.b16 {%0,%1}, [%2];"
                 : "=r"(r0), "=r"(r1) : "r"(a));
}
__device__ __forceinline__ void ldsm_x2t(uint32_t& r0, uint32_t& r1, uint32_t a) {
    asm volatile("ldmatrix.sync.aligned.m8n8.x2.trans.shared.b16 {%0,%1}, [%2];"
                 : "=r"(r0), "=r"(r1) : "r"(a));
}
__device__ __forceinline__ void mma_bf16(float* c, uint32_t a0, uint32_t a1,
                                         uint32_t a2, uint32_t a3,
                                         uint32_t b0, uint32_t b1) {
    asm volatile(
        "mma.sync.aligned.m16n8k16.row.col.f32.bf16.bf16.f32 "
        "{%0,%1,%2,%3}, {%4,%5,%6,%7}, {%8,%9}, {%0,%1,%2,%3};"
        : "+f"(c[0]), "+f"(c[1]), "+f"(c[2]), "+f"(c[3])
        : "r"(a0), "r"(a1), "r"(a2), "r"(a3), "r"(b0), "r"(b1));
}
__device__ __forceinline__ void split2(float x, float y, uint32_t& h, uint32_t& l) {
    bf16 hx = __float2bfloat16_rn(x), hy = __float2bfloat16_rn(y);
    bf16 lx = __float2bfloat16_rn(x - __bfloat162float(hx));
    bf16 ly = __float2bfloat16_rn(y - __bfloat162float(hy));
    __nv_bfloat162 hp; hp.x = hx; hp.y = hy;
    __nv_bfloat162 lp; lp.x = lx; lp.y = ly;
    h = *(uint32_t*)&hp; l = *(uint32_t*)&lp;
}

// ---------------- dense GEMM v2 body (R12 verified config) -----------------
#define TM 128
#define TN 128
#define KC 64
#define STAGES 3
#define GT 256
#define ARR16   16384
#define STGSZ   (4 * ARR16)
#define SM_S    1024
#define GEMM_SMEM (SM_S + STAGES * STGSZ)

template <bool BIAS, bool RELU, bool OUTF, bool OUTS>
__device__ __forceinline__ void gemm_body(
    const bf16* __restrict__ Ah, const bf16* __restrict__ Al,
    const bf16* __restrict__ Bh, const bf16* __restrict__ Bl,
    const float* __restrict__ bias, float* __restrict__ C,
    bf16* __restrict__ Ch, bf16* __restrict__ Cl, int N, int Klen,
    int lda, int koff, int i0, int j0, char* smem)
{
    const uint32_t sbase = cvta_smem(smem);
    const int tid  = threadIdx.x;
    const int lane = tid & 31;
    const int warp = tid >> 5;
    const int wm   = warp >> 2, wn = warp & 3;

    if (BIAS) { if (tid < TN) ((float*)smem)[tid] = bias[j0 + tid]; }

    const int NC = Klen / KC;
    const bf16* srcs[4] = { Ah + (size_t)i0 * lda, Al + (size_t)i0 * lda,
                            Bh + (size_t)j0 * lda, Bl + (size_t)j0 * lda };

    auto load_chunk = [&](int c) {
        const uint32_t stb = sbase + SM_S + (c % STAGES) * STGSZ;
        const int kc = koff + c * KC;
#pragma unroll
        for (int it = 0; it < 16; it++) {
            int s = tid + it * GT;
            int arr = s >> 10, sect = s & 1023;
            int row = sect >> 3, sc = sect & 7;
            cp16(stb + arr * ARR16 + SWZ(row * 128 + sc * 16),
                 (const char*)(srcs[arr] + (size_t)row * lda + kc) + sc * 16);
        }
    };

    float acc[4][4][4];
#pragma unroll
    for (int mt = 0; mt < 4; mt++)
#pragma unroll
        for (int nt = 0; nt < 4; nt++)
#pragma unroll
            for (int e = 0; e < 4; e++) acc[mt][nt][e] = 0.0f;

#pragma unroll
    for (int c = 0; c < STAGES - 1; c++) { load_chunk(c); cp_commit(); }

    const int a_row = wm * 64 + (lane & 15);
    const int a_ko  = (lane >> 4) * 16;
    const int b_row = wn * 32 + (lane & 7);
    const int b_ko  = ((lane >> 3) & 1) * 16;

    for (int c = 0; c < NC; c++) {
        const int cl = c + STAGES - 1;
        if (cl < NC) load_chunk(cl);
        cp_commit();
        cp_wait<STAGES - 1>();
        __syncthreads();
        const uint32_t stb = sbase + SM_S + (c % STAGES) * STGSZ;
#pragma unroll
        for (int ks = 0; ks < 4; ks++) {
            uint32_t bh[4][2], bl[4][2];
#pragma unroll
            for (int nt = 0; nt < 4; nt++) {
                uint32_t off = SWZ((b_row + nt * 8) * 128 + ks * 32 + b_ko);
                ldsm_x2(bh[nt][0], bh[nt][1], stb + 2 * ARR16 + off);
                ldsm_x2(bl[nt][0], bl[nt][1], stb + 3 * ARR16 + off);
            }
#pragma unroll
            for (int mt = 0; mt < 4; mt++) {
                uint32_t off = SWZ((a_row + mt * 16) * 128 + ks * 32 + a_ko);
                uint32_t ah0, ah1, ah2, ah3, al0, al1, al2, al3;
                ldsm_x4(ah0, ah1, ah2, ah3, stb + off);
                ldsm_x4(al0, al1, al2, al3, stb + ARR16 + off);
#pragma unroll
                for (int nt = 0; nt < 4; nt++) {
                    mma_bf16(acc[mt][nt], ah0, ah1, ah2, ah3, bh[nt][0], bh[nt][1]);
                    mma_bf16(acc[mt][nt], ah0, ah1, ah2, ah3, bl[nt][0], bl[nt][1]);
                    mma_bf16(acc[mt][nt], al0, al1, al2, al3, bh[nt][0], bh[nt][1]);
                }
            }
        }
        __syncthreads();
    }

    const int er = lane >> 2, ec = (lane & 3) * 2;
#pragma unroll
    for (int mt = 0; mt < 4; mt++) {
#pragma unroll
        for (int nt = 0; nt < 4; nt++) {
            const int col = wn * 32 + nt * 8 + ec;
            float b0 = 0.0f, b1 = 0.0f;
            if (BIAS) { b0 = ((float*)smem)[col]; b1 = ((float*)smem)[col + 1]; }
#pragma unroll
            for (int h = 0; h < 2; h++) {
                const int row = i0 + wm * 64 + mt * 16 + er + h * 8;
                float v0 = acc[mt][nt][2 * h] + b0;
                float v1 = acc[mt][nt][2 * h + 1] + b1;
                if (RELU) { v0 = fmaxf(v0, 0.0f); v1 = fmaxf(v1, 0.0f); }
                if (OUTF)
                    *(float2*)(C + (size_t)row * N + j0 + col) = make_float2(v0, v1);
                if (OUTS) {
                    uint32_t hh, ll;
                    split2(v0, v1, hh, ll);
                    *(uint32_t*)(Ch + (size_t)row * N + j0 + col) = hh;
                    *(uint32_t*)(Cl + (size_t)row * N + j0 + col) = ll;
                }
            }
        }
    }
}

template <bool BIAS, bool RELU, bool OUTF, bool OUTS>
__global__ __launch_bounds__(GT) void gemm_tc(
    const bf16* __restrict__ Ah, const bf16* __restrict__ Al,
    const bf16* __restrict__ Bh, const bf16* __restrict__ Bl,
    const float* __restrict__ bias, float* __restrict__ C,
    bf16* __restrict__ Ch, bf16* __restrict__ Cl, int N, int K)
{
    extern __shared__ char smem[];
    gemm_body<BIAS, RELU, OUTF, OUTS>(Ah, Al, Bh, Bl, bias, C, Ch, Cl, N, K,
                                      K, 0, blockIdx.y * TM, blockIdx.x * TN, smem);
}

// FF2 split-K=4: grid (8, 32, 4); kz writes fp32 partial kz (no bias)
__global__ __launch_bounds__(GT) void gemm_ff2(
    const bf16* __restrict__ Ah, const bf16* __restrict__ Al,
    const bf16* __restrict__ Bh, const bf16* __restrict__ Bl,
    float* __restrict__ part)
{
    extern __shared__ char smem[];
    const int kz = blockIdx.z;
    gemm_body<false, false, true, false>(
        Ah, Al, Bh, Bl, nullptr,
        part + (size_t)kz * ROWS * DMODEL, nullptr, nullptr,
        DMODEL, DFF / 4, DFF, kz * (DFF / 4),
        blockIdx.y * TM, blockIdx.x * TN, smem);
}

// merged QKV + rk launch (both OUTS-only, K=1024); QKV blocks first
#define QKV_BX (D3 / TN)
#define QKV_BLKS (QKV_BX * (ROWS / TM))
#define RK_BX (DMODEL / TN)
#define TOT_BLKS (QKV_BLKS + RK_BX * (QLEN / TM))

__global__ __launch_bounds__(GT) void gemm_qkv_rk(
    const bf16* __restrict__ wh, const bf16* __restrict__ wl,
    const bf16* __restrict__ qwh, const bf16* __restrict__ qwl,
    bf16* __restrict__ hh, bf16* __restrict__ hl,
    const bf16* __restrict__ rh, const bf16* __restrict__ rl,
    const bf16* __restrict__ rwh, const bf16* __restrict__ rwl,
    bf16* __restrict__ rkh, bf16* __restrict__ rkl)
{
    extern __shared__ char smem[];
    const int bid = blockIdx.x;
    if (bid < QKV_BLKS) {
        gemm_body<false, false, false, true>(
            wh, wl, qwh, qwl, nullptr, nullptr, hh, hl, D3, DMODEL,
            DMODEL, 0, (bid / QKV_BX) * TM, (bid % QKV_BX) * TN, smem);
    } else {
        const int b2 = bid - QKV_BLKS;
        gemm_body<false, false, false, true>(
            rh, rl, rwh, rwl, nullptr, nullptr, rkh, rkl, DMODEL, DMODEL,
            DMODEL, 0, (b2 / RK_BX) * TM, (b2 % RK_BX) * TN, smem);
    }
}

// -------- batched split: all 7 tensors, descriptors passed BY VALUE --------
struct SplitDesc { const float4* x; uint2* h; uint2* l; int base; int pad; };
struct SplitArgs { SplitDesc d[7]; };

__global__ __launch_bounds__(256) void split_all(SplitArgs args, int total4)
{
    int i = blockIdx.x * 256 + threadIdx.x;
    if (i >= total4) return;
    int seg = 0;
#pragma unroll
    for (int s = 1; s < 7; s++) if (i >= args.d[s].base) seg = s;
    int k = i - args.d[seg].base;
    float4 v = args.d[seg].x[k];
    uint32_t h01, l01, h23, l23;
    split2(v.x, v.y, h01, l01);
    split2(v.z, v.w, h23, l23);
    args.d[seg].h[k] = make_uint2(h01, h23);
    args.d[seg].l[k] = make_uint2(l01, l23);
}

// ------------------------- fused flash attention (R8) ----------------------
#define FQWH 0
#define FQWL 8192
#define FQRH 16384
#define FQRL 24576
#define FKV  32768
#define FRK  98304
#define FDT  163840
#define FSTM 197632
#define FSTS 198144
#define FLASH_SMEM 198656

__global__ __launch_bounds__(256) void flash_attn(
    const bf16* __restrict__ hh, const bf16* __restrict__ hl,
    const bf16* __restrict__ rkh, const bf16* __restrict__ rkl,
    const float* __restrict__ rwb, const float* __restrict__ rrb,
    bf16* __restrict__ avh, bf16* __restrict__ avl)
{
    extern __shared__ char sm[];
    const uint32_t sb = cvta_smem(sm);
    const int tid = threadIdx.x, lane = tid & 31, w = tid >> 5;
    const int wr = w >> 1, wc = w & 1;
    const int ib = 15 - (int)blockIdx.x;
    const int bn = blockIdx.y, b = bn >> 4, n = bn & 15;
    const int i0 = ib * 64;
    const int tw0 = QLEN - 64 - i0;
    const int ntiles = ib + 1;
    const size_t bq = (size_t)b * QLEN;
    const int barid = wr + 1;

    auto load_kv = [&](int jt) {
        const uint32_t dstb = sb + FKV + (jt & 1) * 32768;
#pragma unroll
        for (int it = 0; it < 8; it++) {
            int s = tid + it * 256;
            int arr = s >> 9, sect = s & 511;
            int row = sect >> 3, sc = sect & 7;
            const bf16* src = ((arr & 1) ? hl : hh) +
                (bq + jt * 64 + row) * D3 + ((arr >> 1) + 1) * DMODEL + n * 64;
            cp16(dstb + arr * 8192 + SWZ(row * 128 + sc * 16),
                 (const char*)src + sc * 16);
        }
    };
    auto load_rk = [&](int tile) {
        const uint32_t dstb = sb + FRK + (tile & 3) * 16384;
#pragma unroll
        for (int it = 0; it < 4; it++) {
            int s = tid + it * 256;
            int arr = s >> 9, sect = s & 511;
            int row = sect >> 3, sc = sect & 7;
            int t = tw0 + tile * 64 + row;
            int tc = (t < QLEN) ? t : 0;
            const bf16* src = (arr ? rkl : rkh) + (size_t)tc * DMODEL + n * 64;
            cp16z(dstb + arr * 8192 + SWZ(row * 128 + sc * 16),
                  (const char*)src + sc * 16, (t < QLEN) ? 16u : 0u);
        }
    };

    load_kv(0); load_rk(0); load_rk(1); cp_commit();

#pragma unroll
    for (int it = 0; it < 4; it++) {
        int s = tid + it * 256;
        int row = s >> 4, c4 = (s & 15) << 2;
        const size_t qoff = (bq + i0 + row) * D3 + n * 64 + c4;
        uint2 qh = *(const uint2*)(hh + qoff);
        uint2 ql = *(const uint2*)(hl + qoff);
        __nv_bfloat162 h01 = *(__nv_bfloat162*)&qh.x, h23 = *(__nv_bfloat162*)&qh.y;
        __nv_bfloat162 l01 = *(__nv_bfloat162*)&ql.x, l23 = *(__nv_bfloat162*)&ql.y;
        float q0 = __bfloat162float(h01.x) + __bfloat162float(l01.x);
        float q1 = __bfloat162float(h01.y) + __bfloat162float(l01.y);
        float q2 = __bfloat162float(h23.x) + __bfloat162float(l23.x);
        float q3 = __bfloat162float(h23.y) + __bfloat162float(l23.y);
        float4 bw = *(const float4*)(rwb + n * 64 + c4);
        float4 br = *(const float4*)(rrb + n * 64 + c4);
        uint32_t a01, b01, a23, b23;
        uint32_t off = SWZ(row * 128 + c4 * 2);
        split2((q0 + bw.x) * 0.125f, (q1 + bw.y) * 0.125f, a01, b01);
        split2((q2 + bw.z) * 0.125f, (q3 + bw.w) * 0.125f, a23, b23);
        *(uint2*)(sm + FQWH + off) = make_uint2(a01, a23);
        *(uint2*)(sm + FQWL + off) = make_uint2(b01, b23);
        split2((q0 + br.x) * 0.125f, (q1 + br.y) * 0.125f, a01, b01);
        split2((q2 + br.z) * 0.125f, (q3 + br.w) * 0.125f, a23, b23);
        *(uint2*)(sm + FQRH + off) = make_uint2(a01, a23);
        *(uint2*)(sm + FQRL + off) = make_uint2(b01, b23);
    }

    float m0 = -INFINITY, m1 = -INFINITY, l0 = 0.0f, l1 = 0.0f;
    float accO[8][4];
#pragma unroll
    for (int nt = 0; nt < 8; nt++)
#pragma unroll
        for (int e = 0; e < 4; e++) accO[nt][e] = 0.0f;

    const int r0 = lane >> 2, c00 = (lane & 3) * 2;
    const uint32_t aoff = (wr * 16 + (lane & 15)) * 128 + ((lane >> 4) << 4);
    const uint32_t bko  = ((lane >> 3) & 1) << 4;
    const int u0 = 6 - 2 * wr;
    float* dwp = (float*)(sm + FDT + wr * 8448);
    float* stM = (float*)(sm + FSTM);
    float* stS = (float*)(sm + FSTS);

    for (int jt = 0; jt < ntiles; jt++) {
        cp_wait<0>();
        __syncthreads();
        if (jt + 1 < ntiles) { load_kv(jt + 1); load_rk(jt + 2); }
        cp_commit();

        const uint32_t kvb = sb + FKV + (jt & 1) * 32768;
        float aS[4][4];
#pragma unroll
        for (int nt = 0; nt < 4; nt++)
#pragma unroll
            for (int e = 0; e < 4; e++) aS[nt][e] = 0.0f;
#pragma unroll
        for (int kc = 0; kc < 4; kc++) {
            uint32_t ah0, ah1, ah2, ah3, al0, al1, al2, al3;
            ldsm_x4(ah0, ah1, ah2, ah3, sb + FQWH + SWZ(aoff + kc * 32));
            ldsm_x4(al0, al1, al2, al3, sb + FQWL + SWZ(aoff + kc * 32));
#pragma unroll
            for (int nt = 0; nt < 4; nt++) {
                uint32_t boff = (wc * 32 + nt * 8 + (lane & 7)) * 128 + kc * 32 + bko;
                uint32_t b0, b1;
                ldsm_x2(b0, b1, kvb + SWZ(boff));
                mma_bf16(aS[nt], ah0, ah1, ah2, ah3, b0, b1);
                mma_bf16(aS[nt], al0, al1, al2, al3, b0, b1);
                ldsm_x2(b0, b1, kvb + 8192 + SWZ(boff));
                mma_bf16(aS[nt], ah0, ah1, ah2, ah3, b0, b1);
            }
        }

        float aB[5][4];
#pragma unroll
        for (int v = 0; v < 5; v++)
#pragma unroll
            for (int e = 0; e < 4; e++) aB[v][e] = 0.0f;
#pragma unroll
        for (int kc = 0; kc < 4; kc++) {
            uint32_t ah0, ah1, ah2, ah3, al0, al1, al2, al3;
            ldsm_x4(ah0, ah1, ah2, ah3, sb + FQRH + SWZ(aoff + kc * 32));
            ldsm_x4(al0, al1, al2, al3, sb + FQRL + SWZ(aoff + kc * 32));
#pragma unroll
            for (int v = 0; v < 5; v++) {
                int cu = u0 + wc * 5 + v;
                uint32_t rbase = sb + FRK + ((jt + (cu >> 3)) & 3) * 16384;
                uint32_t boff = ((cu & 7) * 8 + (lane & 7)) * 128 + kc * 32 + bko;
                uint32_t b0, b1;
                ldsm_x2(b0, b1, rbase + SWZ(boff));
                mma_bf16(aB[v], ah0, ah1, ah2, ah3, b0, b1);
                mma_bf16(aB[v], al0, al1, al2, al3, b0, b1);
                ldsm_x2(b0, b1, rbase + 8192 + SWZ(boff));
                mma_bf16(aB[v], ah0, ah1, ah2, ah3, b0, b1);
            }
        }
#pragma unroll
        for (int v = 0; v < 5; v++) {
            int col = (u0 + wc * 5 + v) * 8 + c00;
            dwp[r0 * 132 + col]           = aB[v][0];
            dwp[r0 * 132 + col + 1]       = aB[v][1];
            dwp[(r0 + 8) * 132 + col]     = aB[v][2];
            dwp[(r0 + 8) * 132 + col + 1] = aB[v][3];
        }
        bar_pair(barid);

        const int s0 = 63 - wr * 16 - r0, s1 = s0 - 8;
        const int gi0 = i0 + wr * 16 + r0, gi1 = gi0 + 8;
        const int j0 = jt * 64;
        float tm0 = -INFINITY, tm1 = -INFINITY;
#pragma unroll
        for (int nt = 0; nt < 4; nt++) {
            int cb = wc * 32 + nt * 8 + c00;
            float v0 = aS[nt][0] + dwp[r0 * 132 + cb + s0];
            float v1 = aS[nt][1] + dwp[r0 * 132 + cb + 1 + s0];
            float v2 = aS[nt][2] + dwp[(r0 + 8) * 132 + cb + s1];
            float v3 = aS[nt][3] + dwp[(r0 + 8) * 132 + cb + 1 + s1];
            if (j0 + cb     > gi0) v0 = -INFINITY;
            if (j0 + cb + 1 > gi0) v1 = -INFINITY;
            if (j0 + cb     > gi1) v2 = -INFINITY;
            if (j0 + cb + 1 > gi1) v3 = -INFINITY;
            aS[nt][0] = v0; aS[nt][1] = v1; aS[nt][2] = v2; aS[nt][3] = v3;
            tm0 = fmaxf(tm0, fmaxf(v0, v1));
            tm1 = fmaxf(tm1, fmaxf(v2, v3));
        }
        tm0 = fmaxf(tm0, __shfl_xor_sync(0xffffffffu, tm0, 1));
        tm0 = fmaxf(tm0, __shfl_xor_sync(0xffffffffu, tm0, 2));
        tm1 = fmaxf(tm1, __shfl_xor_sync(0xffffffffu, tm1, 1));
        tm1 = fmaxf(tm1, __shfl_xor_sync(0xffffffffu, tm1, 2));
        if ((lane & 3) == 0) {
            stM[(wr * 16 + r0) * 2 + wc]     = tm0;
            stM[(wr * 16 + r0 + 8) * 2 + wc] = tm1;
        }
        bar_pair(barid);
        float cm0 = fmaxf(stM[(wr * 16 + r0) * 2],     stM[(wr * 16 + r0) * 2 + 1]);
        float cm1 = fmaxf(stM[(wr * 16 + r0 + 8) * 2], stM[(wr * 16 + r0 + 8) * 2 + 1]);
        float mn0 = fmaxf(m0, cm0), mn1 = fmaxf(m1, cm1);
        float sc0 = __expf(m0 - mn0), sc1 = __expf(m1 - mn1);
        m0 = mn0; m1 = mn1;
        float ts0 = 0.0f, ts1 = 0.0f;
#pragma unroll
        for (int nt = 0; nt < 4; nt++) {
            float p0 = __expf(aS[nt][0] - m0);
            float p1 = __expf(aS[nt][1] - m0);
            float p2 = __expf(aS[nt][2] - m1);
            float p3 = __expf(aS[nt][3] - m1);
            aS[nt][0] = p0; aS[nt][1] = p1; aS[nt][2] = p2; aS[nt][3] = p3;
            ts0 += p0 + p1; ts1 += p2 + p3;
        }
        ts0 += __shfl_xor_sync(0xffffffffu, ts0, 1);
        ts0 += __shfl_xor_sync(0xffffffffu, ts0, 2);
        ts1 += __shfl_xor_sync(0xffffffffu, ts1, 1);
        ts1 += __shfl_xor_sync(0xffffffffu, ts1, 2);
        if ((lane & 3) == 0) {
            stS[(wr * 16 + r0) * 2 + wc]     = ts0;
            stS[(wr * 16 + r0 + 8) * 2 + wc] = ts1;
        }
        bar_pair(barid);
        float cs0 = stS[(wr * 16 + r0) * 2]     + stS[(wr * 16 + r0) * 2 + 1];
        float cs1 = stS[(wr * 16 + r0 + 8) * 2] + stS[(wr * 16 + r0 + 8) * 2 + 1];
        l0 = l0 * sc0 + cs0;
        l1 = l1 * sc1 + cs1;
#pragma unroll
        for (int nt = 0; nt < 8; nt++) {
            accO[nt][0] *= sc0; accO[nt][1] *= sc0;
            accO[nt][2] *= sc1; accO[nt][3] *= sc1;
        }

        uint32_t ph[2][4], pl[2][4];
#pragma unroll
        for (int kcl = 0; kcl < 2; kcl++) {
            split2(aS[2*kcl][0],   aS[2*kcl][1],   ph[kcl][0], pl[kcl][0]);
            split2(aS[2*kcl][2],   aS[2*kcl][3],   ph[kcl][1], pl[kcl][1]);
            split2(aS[2*kcl+1][0], aS[2*kcl+1][1], ph[kcl][2], pl[kcl][2]);
            split2(aS[2*kcl+1][2], aS[2*kcl+1][3], ph[kcl][3], pl[kcl][3]);
        }
#pragma unroll
        for (int kcl = 0; kcl < 2; kcl++) {
            uint32_t voff = (wc * 32 + kcl * 16 + (lane & 15)) * 128;
#pragma unroll
            for (int vnt = 0; vnt < 8; vnt++) {
                uint32_t b0, b1;
                ldsm_x2t(b0, b1, kvb + 16384 + SWZ(voff + vnt * 16));
                mma_bf16(accO[vnt], ph[kcl][0], ph[kcl][1], ph[kcl][2], ph[kcl][3], b0, b1);
                mma_bf16(accO[vnt], pl[kcl][0], pl[kcl][1], pl[kcl][2], pl[kcl][3], b0, b1);
                ldsm_x2t(b0, b1, kvb + 24576 + SWZ(voff + vnt * 16));
                mma_bf16(accO[vnt], ph[kcl][0], ph[kcl][1], ph[kcl][2], ph[kcl][3], b0, b1);
            }
        }
    }

    float* red = (float*)(sm + FDT + wr * 4096);
    if (wc == 1) {
#pragma unroll
        for (int nt = 0; nt < 8; nt++)
#pragma unroll
            for (int e = 0; e < 4; e++)
                red[(nt * 4 + e) * 32 + lane] = accO[nt][e];
    }
    __syncthreads();
    if (wc == 0) {
#pragma unroll
        for (int nt = 0; nt < 8; nt++)
#pragma unroll
            for (int e = 0; e < 4; e++)
                accO[nt][e] += red[(nt * 4 + e) * 32 + lane];
        const float inv0 = 1.0f / l0, inv1 = 1.0f / l1;
        const size_t row0 = (bq + i0 + wr * 16 + r0) * DMODEL + n * 64;
        const size_t row1 = row0 + 8 * DMODEL;
#pragma unroll
        for (int nt = 0; nt < 8; nt++) {
            int col = nt * 8 + c00;
            uint32_t hh2, ll2;
            split2(accO[nt][0] * inv0, accO[nt][1] * inv0, hh2, ll2);
            *(uint32_t*)(avh + row0 + col) = hh2;
            *(uint32_t*)(avl + row0 + col) = ll2;
            split2(accO[nt][2] * inv1, accO[nt][3] * inv1, hh2, ll2);
            *(uint32_t*)(avh + row1 + col) = hh2;
            *(uint32_t*)(avl + row1 + col) = ll2;
        }
    }
}

// ------------------------- residual + LayerNorm (2 rows/CTA) ---------------
template <bool SPLIT>
__global__ __launch_bounds__(512) void add_ln(
    const float* __restrict__ a, const float* __restrict__ bb,
    const float* __restrict__ gamma, const float* __restrict__ beta,
    float* __restrict__ out, bf16* __restrict__ oh, bf16* __restrict__ ol)
{
    const int row = blockIdx.x * 2 + (threadIdx.x >> 8);
    const size_t base = (size_t)row * DMODEL;
    const int tid = threadIdx.x & 255;
    const int half = threadIdx.x >> 8;
    __shared__ float red[2][8];

    float x[4];
    float sum = 0.0f;
#pragma unroll
    for (int c = 0; c < 4; c++) {
        int j = tid + (c << 8);
        x[c] = a[base + j] + bb[base + j];
        sum += x[c];
    }
#pragma unroll
    for (int o = 16; o; o >>= 1) sum += __shfl_xor_sync(0xffffffffu, sum, o);
    if ((tid & 31) == 0) red[half][tid >> 5] = sum;
    __syncthreads();
    float tot = red[half][0];
#pragma unroll
    for (int w = 1; w < 8; w++) tot += red[half][w];
    __syncthreads();
    const float mean = tot * (1.0f / DMODEL);

    float vs = 0.0f;
#pragma unroll
    for (int c = 0; c < 4; c++) { float d = x[c] - mean; vs += d * d; }
#pragma unroll
    for (int o = 16; o; o >>= 1) vs += __shfl_xor_sync(0xffffffffu, vs, o);
    if ((tid & 31) == 0) red[half][tid >> 5] = vs;
    __syncthreads();
    float vtot = red[half][0];
#pragma unroll
    for (int w = 1; w < 8; w++) vtot += red[half][w];
    const float rstd = rsqrtf(vtot * (1.0f / DMODEL) + 1e-5f);

#pragma unroll
    for (int c = 0; c < 4; c++) {
        int j = tid + (c << 8);
        float y = (x[c] - mean) * rstd * gamma[j] + beta[j];
        out[base + j] = y;
        if (SPLIT) {
            bf16 h = __float2bfloat16_rn(y);
            bf16 l = __float2bfloat16_rn(y - __bfloat162float(h));
            oh[base + j] = h; ol[base + j] = l;
        }
    }
}

// LN2 with fused split-K reduction: out = LN(a + Σ4 parts + bias2)
__global__ __launch_bounds__(512) void add_ln4(
    const float* __restrict__ a, const float* __restrict__ part,
    const float* __restrict__ bias2,
    const float* __restrict__ gamma, const float* __restrict__ beta,
    float* __restrict__ out)
{
    const int row = blockIdx.x * 2 + (threadIdx.x >> 8);
    const size_t base = (size_t)row * DMODEL;
    const int tid = threadIdx.x & 255;
    const int half = threadIdx.x >> 8;
    __shared__ float red[2][8];
    const size_t PS = (size_t)ROWS * DMODEL;

    float x[4];
    float sum = 0.0f;
#pragma unroll
    for (int c = 0; c < 4; c++) {
        int j = tid + (c << 8);
        float v = a[base + j] + bias2[j];
        v += part[base + j] + part[PS + base + j];
        v += part[2 * PS + base + j] + part[3 * PS + base + j];
        x[c] = v;
        sum += v;
    }
#pragma unroll
    for (int o = 16; o; o >>= 1) sum += __shfl_xor_sync(0xffffffffu, sum, o);
    if ((tid & 31) == 0) red[half][tid >> 5] = sum;
    __syncthreads();
    float tot = red[half][0];
#pragma unroll
    for (int w = 1; w < 8; w++) tot += red[half][w];
    __syncthreads();
    const float mean = tot * (1.0f / DMODEL);

    float vs = 0.0f;
#pragma unroll
    for (int c = 0; c < 4; c++) { float d = x[c] - mean; vs += d * d; }
#pragma unroll
    for (int o = 16; o; o >>= 1) vs += __shfl_xor_sync(0xffffffffu, vs, o);
    if ((tid & 31) == 0) red[half][tid >> 5] = vs;
    __syncthreads();
    float vtot = red[half][0];
#pragma unroll
    for (int w = 1; w < 8; w++) vtot += red[half][w];
    const float rstd = rsqrtf(vtot * (1.0f / DMODEL) + 1e-5f);

#pragma unroll
    for (int c = 0; c < 4; c++) {
        int j = tid + (c << 8);
        out[base + j] = (x[c] - mean) * rstd * gamma[j] + beta[j];
    }
}

// ------------------------------- launcher ----------------------------------
extern "C" void kernel_launch(void* const* d_in, const int* in_sizes, int n_in,
                              void* d_out, int out_size)
{
    (void)in_sizes; (void)n_in; (void)out_size;

    const float* w        = (const float*)d_in[0];
    const float* r        = (const float*)d_in[1];
    const float* qkv_w    = (const float*)d_in[3];
    const float* r_w      = (const float*)d_in[4];
    const float* o_w      = (const float*)d_in[5];
    const float* r_w_bias = (const float*)d_in[6];
    const float* r_r_bias = (const float*)d_in[7];
    const float* ln1_g    = (const float*)d_in[8];
    const float* ln1_b    = (const float*)d_in[9];
    const float* ff_w1    = (const float*)d_in[10];
    const float* ff_b1    = (const float*)d_in[11];
    const float* ff_w2    = (const float*)d_in[12];
    const float* ff_b2    = (const float*)d_in[13];
    const float* ln2_g    = (const float*)d_in[14];
    const float* ln2_b    = (const float*)d_in[15];
    float* out = (float*)d_out;

    float *tmp, *out1, *pt;
    cudaGetSymbolAddress((void**)&tmp,  g_tmp);
    cudaGetSymbolAddress((void**)&out1, g_out1);
    cudaGetSymbolAddress((void**)&pt,   g_pt);

    bf16 *wh, *wl, *rh, *rl, *qwh, *qwl, *rwh, *rwl, *owh, *owl;
    bf16 *f1h, *f1l, *f2h, *f2l, *avh, *avl, *o1h, *o1l, *ff1h, *ff1l;
    bf16 *hh, *hl, *rkh, *rkl;
    cudaGetSymbolAddress((void**)&wh,  g_wh);  cudaGetSymbolAddress((void**)&wl,  g_wl);
    cudaGetSymbolAddress((void**)&rh,  g_rh);  cudaGetSymbolAddress((void**)&rl,  g_rl);
    cudaGetSymbolAddress((void**)&qwh, g_qwh); cudaGetSymbolAddress((void**)&qwl, g_qwl);
    cudaGetSymbolAddress((void**)&rwh, g_rwh); cudaGetSymbolAddress((void**)&rwl, g_rwl);
    cudaGetSymbolAddress((void**)&owh, g_owh); cudaGetSymbolAddress((void**)&owl, g_owl);
    cudaGetSymbolAddress((void**)&f1h, g_f1h); cudaGetSymbolAddress((void**)&f1l, g_f1l);
    cudaGetSymbolAddress((void**)&f2h, g_f2h); cudaGetSymbolAddress((void**)&f2l, g_f2l);
    cudaGetSymbolAddress((void**)&avh, g_avh); cudaGetSymbolAddress((void**)&avl, g_avl);
    cudaGetSymbolAddress((void**)&o1h, g_o1h); cudaGetSymbolAddress((void**)&o1l, g_o1l);
    cudaGetSymbolAddress((void**)&ff1h, g_ff1h); cudaGetSymbolAddress((void**)&ff1l, g_ff1l);
    cudaGetSymbolAddress((void**)&hh,  g_hh);  cudaGetSymbolAddress((void**)&hl,  g_hl);
    cudaGetSymbolAddress((void**)&rkh, g_rkh); cudaGetSymbolAddress((void**)&rkl, g_rkl);

    cudaFuncSetAttribute(gemm_qkv_rk,
                         cudaFuncAttributeMaxDynamicSharedMemorySize, GEMM_SMEM);
    cudaFuncSetAttribute(gemm_ff2,
                         cudaFuncAttributeMaxDynamicSharedMemorySize, GEMM_SMEM);
    cudaFuncSetAttribute(gemm_tc<false, false, true, false>,
                         cudaFuncAttributeMaxDynamicSharedMemorySize, GEMM_SMEM);
    cudaFuncSetAttribute(gemm_tc<true, true, false, true>,
                         cudaFuncAttributeMaxDynamicSharedMemorySize, GEMM_SMEM);
    cudaFuncSetAttribute(flash_attn,
                         cudaFuncAttributeMaxDynamicSharedMemorySize, FLASH_SMEM);

    // one batched split launch; descriptors passed by value (graph-safe)
    {
        SplitArgs sa;
        const float* xs[7] = { w, r, qkv_w, r_w, o_w, ff_w1, ff_w2 };
        bf16* hs[7] = { wh, rh, qwh, rwh, owh, f1h, f2h };
        bf16* ls[7] = { wl, rl, qwl, rwl, owl, f1l, f2l };
        size_t ns[7] = { (size_t)ROWS * DMODEL, (size_t)QLEN * DMODEL,
                         (size_t)D3 * DMODEL, (size_t)DMODEL * DMODEL,
                         (size_t)DMODEL * DMODEL, (size_t)DFF * DMODEL,
                         (size_t)DMODEL * DFF };
        int base = 0;
        for (int s = 0; s < 7; s++) {
            sa.d[s].x = (const float4*)xs[s];
            sa.d[s].h = (uint2*)hs[s];
            sa.d[s].l = (uint2*)ls[s];
            sa.d[s].base = base;
            sa.d[s].pad = 0;
            base += (int)(ns[s] / 4);
        }
        split_all<<<(base + 255) / 256, 256>>>(sa, base);
    }

    const dim3 blk(256);
    // merged QKV + rk GEMM
    gemm_qkv_rk<<<TOT_BLKS, blk, GEMM_SMEM>>>(
        wh, wl, qwh, qwl, hh, hl, rh, rl, rwh, rwl, rkh, rkl);

    flash_attn<<<dim3(16, 64), dim3(256), FLASH_SMEM>>>(
        hh, hl, rkh, rkl, r_w_bias, r_r_bias, avh, avl);

    gemm_tc<false, false, true, false><<<dim3(DMODEL / TN, ROWS / TM), blk, GEMM_SMEM>>>(
        avh, avl, owh, owl, nullptr, tmp, nullptr, nullptr, DMODEL, DMODEL);

    add_ln<true><<<ROWS / 2, 512>>>(w, tmp, ln1_g, ln1_b, out1, o1h, o1l);

    gemm_tc<true, true, false, true><<<dim3(DFF / TN, ROWS / TM), blk, GEMM_SMEM>>>(
        o1h, o1l, f1h, f1l, ff_b1, nullptr, ff1h, ff1l, DFF, DMODEL);

    // FF2 split-K=4 -> fp32 partials
    gemm_ff2<<<dim3(DMODEL / TN, ROWS / TM, 4), blk, GEMM_SMEM>>>(
        ff1h, ff1l, f2h, f2l, pt);

    // out = LN(out1 + Σ partials + b2)
    add_ln4<<<ROWS / 2, 512>>>(out1, pt, ff_b2, ln2_g, ln2_b, out);
}